// round 12
// baseline (speedup 1.0000x reference)
#include <cuda_runtime.h>
#include <cuda_fp16.h>

#define NN 100000
#define NE 1600000
#define NG 1000
#define CAP 64

// ---------------- scratch (device globals; zero-initialized at load) ----------------
__device__ float  d_h[NN * 64];
__device__ float  d_p[NN * 64];     // float2-interleaved: ((float2*)d_p)[n*32+lane] = {f, f+32}
__device__ float  d_u[NN * 64];
__device__ float  d_agg[NN * 64];
__device__ __half d_attrH[NE * 16]; // fp16 copy of edge_attr (row-major, 32B/row)
__device__ float  d_gpool[NG * 64];
__device__ int    d_gcnt[NG];
__device__ int    d_cnt[NN];          // zero-init; re-zeroed by k_pool each run
__device__ int2   d_se[NN * CAP + 8]; // per-dst bucket of (src, eid); +8 pad for ahead-loads
__device__ float  d_C[3 * 16 * 64];
__device__ float  d_cv[3 * 64];
__device__ double d_stats[3 * 256];   // per layer: msgSum64,msgSq64,updSum64,updSq64; cleaned by k_scatter

__device__ __forceinline__ unsigned pkh2(float lo, float hi) {
    __half2 h = __floats2half2_rn(lo, hi);
    return *reinterpret_cast<unsigned*>(&h);
}
__device__ __forceinline__ float2 h2f(unsigned u) {
    return __half22float2(*reinterpret_cast<__half2*>(&u));
}

// launch 0: bucket scatter + fp16 attr conversion + stats cleanup (for this call)
__global__ __launch_bounds__(256) void k_scatter(const int* __restrict__ src,
                                                 const int* __restrict__ dst,
                                                 const float* __restrict__ attr) {
    int tid0 = blockIdx.x * blockDim.x + threadIdx.x;
    if (tid0 < 3 * 256) d_stats[tid0] = 0.0;
    int stride = gridDim.x * blockDim.x;
    for (int i = tid0; i < NE; i += stride) {
        int d = dst[i];
        int pos = atomicAdd(&d_cnt[d], 1);
        if (pos < CAP) d_se[d * CAP + pos] = make_int2(src[i], i);
    }
    for (int i = tid0; i < NE; i += stride) {
        const float4* a4 = (const float4*)(attr + (size_t)i * 16);
        float4 v0 = a4[0], v1 = a4[1], v2 = a4[2], v3 = a4[3];
        uint4 o0, o1;
        o0.x = pkh2(v0.x, v0.y); o0.y = pkh2(v0.z, v0.w);
        o0.z = pkh2(v1.x, v1.y); o0.w = pkh2(v1.z, v1.w);
        o1.x = pkh2(v2.x, v2.y); o1.y = pkh2(v2.z, v2.w);
        o1.z = pkh2(v3.x, v3.y); o1.w = pkh2(v3.z, v3.w);
        uint4* hp = (uint4*)(d_attrH + (size_t)i * 16);
        hp[0] = o0; hp[1] = o1;
    }
}

// launch 1: embed (warp per node, weights in regs) + composite-C (last block)
#define EM_BLOCKS 512
__global__ __launch_bounds__(256) void k_embed(const float* __restrict__ x,
                                               const float* __restrict__ node_W,
                                               const float* __restrict__ node_b,
                                               const float* __restrict__ edge_W,
                                               const float* __restrict__ edge_b,
                                               const float* __restrict__ msg_W,
                                               const float* __restrict__ msg_b) {
    int b = blockIdx.x;
    if (b < EM_BLOCKS) {
        int lane = threadIdx.x & 31;
        float w0[32], w1[32];
#pragma unroll
        for (int k = 0; k < 32; k++) { w0[k] = node_W[k * 64 + lane]; w1[k] = node_W[k * 64 + lane + 32]; }
        float b0 = node_b[lane], b1 = node_b[lane + 32];
        int gw = (b * 256 + threadIdx.x) >> 5;
        int nw = (EM_BLOCKS * 256) >> 5;
        for (int n = gw; n < NN; n += nw) {
            float xv = x[n * 32 + lane];
            float a0 = b0, a1 = b1;
#pragma unroll
            for (int k = 0; k < 32; k++) {
                float bc = __shfl_sync(0xffffffffu, xv, k);
                a0 = fmaf(bc, w0[k], a0); a1 = fmaf(bc, w1[k], a1);
            }
            d_h[n * 64 + lane] = a0; d_h[n * 64 + lane + 32] = a1;
        }
    } else {
        int t = threadIdx.x;
        if (t < 192) {
            int l = t >> 6, f = t & 63;
            const float* Wm = msg_W + l * 96 * 64 + 64 * 64;
            for (int kk = 0; kk < 16; kk++) {
                float s = 0.f;
                for (int j = 0; j < 32; j++) s = fmaf(edge_W[kk * 32 + j], Wm[j * 64 + f], s);
                d_C[l * 1024 + kk * 64 + f] = s;
            }
            float cv = msg_b[l * 64 + f];
            for (int j = 0; j < 32; j++) cv = fmaf(edge_b[j], Wm[j * 64 + f], cv);
            d_cv[l * 64 + f] = cv;
        }
    }
}

// p = in @ msg_W[l][0:64,:] (prev-layer BN affine computed inline from stats, folded)
__global__ __launch_bounds__(256) void k_p(const float* __restrict__ msg_W, int l,
                                           const float* __restrict__ upd_gamma,
                                           const float* __restrict__ upd_beta) {
    __shared__ float ssc[64], ssh[64];
    if (l > 0 && threadIdx.x < 64) {
        int f = threadIdx.x;
        const double* st = d_stats + (l - 1) * 256 + 128;
        double mu  = st[f] / (double)NN;
        double var = st[64 + f] / (double)NN - mu * mu;
        float sc = upd_gamma[(l - 1) * 64 + f] * rsqrtf((float)var + 1e-5f);
        ssc[f] = sc;
        ssh[f] = upd_beta[(l - 1) * 64 + f] - (float)mu * sc;
    }
    __syncthreads();
    const float* W = msg_W + l * 96 * 64;
    const float* in = (l == 0) ? d_h : d_u;
    int lane = threadIdx.x & 31;
    int half = (threadIdx.x >> 5) & 1;
    int pib  = threadIdx.x >> 6;
    float w0[32], w1[32];
    float bias0 = 0.f, bias1 = 0.f;
#pragma unroll
    for (int kk = 0; kk < 32; kk++) {
        int k = half * 32 + kk;
        float wa = W[k * 64 + lane], wb = W[k * 64 + lane + 32];
        if (l > 0) {
            bias0 = fmaf(ssh[k], wa, bias0); bias1 = fmaf(ssh[k], wb, bias1);
            float s = ssc[k]; wa *= s; wb *= s;
        }
        w0[kk] = wa; w1[kk] = wb;
    }
    __shared__ float2 red[4][32];
    float2* p2 = (float2*)d_p;
    int stride = gridDim.x * 4;
    for (int nb = blockIdx.x * 4; nb < NN; nb += stride) {
        int n = nb + pib;
        bool act = (n < NN);
        float a0 = bias0, a1 = bias1;
        if (act) {
            float hv = in[n * 64 + half * 32 + lane];
#pragma unroll
            for (int kk = 0; kk < 32; kk++) {
                float bc = __shfl_sync(0xffffffffu, hv, kk);
                a0 = fmaf(bc, w0[kk], a0); a1 = fmaf(bc, w1[kk], a1);
            }
        }
        if (half == 1) red[pib][lane] = make_float2(a0, a1);
        __syncthreads();
        if (act && half == 0) {
            float2 o = red[pib][lane];
            p2[(size_t)n * 32 + lane] = make_float2(a0 + o.x, a1 + o.y);
        }
        __syncthreads();
    }
}

// dual 16-step fp16-attr FMA chain (attr row in two uint4)
#define MCHAIN(Ha, Hb, P, OUT0, OUT1) do {                                        \
    float m0 = (P).x + cb0, m1 = (P).y + cb1; float2 t;                           \
    t = h2f((Ha).x); m0 = fmaf(t.x, cw0[0], m0);  m1 = fmaf(t.x, cw1[0], m1);     \
                     m0 = fmaf(t.y, cw0[1], m0);  m1 = fmaf(t.y, cw1[1], m1);     \
    t = h2f((Ha).y); m0 = fmaf(t.x, cw0[2], m0);  m1 = fmaf(t.x, cw1[2], m1);     \
                     m0 = fmaf(t.y, cw0[3], m0);  m1 = fmaf(t.y, cw1[3], m1);     \
    t = h2f((Ha).z); m0 = fmaf(t.x, cw0[4], m0);  m1 = fmaf(t.x, cw1[4], m1);     \
                     m0 = fmaf(t.y, cw0[5], m0);  m1 = fmaf(t.y, cw1[5], m1);     \
    t = h2f((Ha).w); m0 = fmaf(t.x, cw0[6], m0);  m1 = fmaf(t.x, cw1[6], m1);     \
                     m0 = fmaf(t.y, cw0[7], m0);  m1 = fmaf(t.y, cw1[7], m1);     \
    t = h2f((Hb).x); m0 = fmaf(t.x, cw0[8], m0);  m1 = fmaf(t.x, cw1[8], m1);     \
                     m0 = fmaf(t.y, cw0[9], m0);  m1 = fmaf(t.y, cw1[9], m1);     \
    t = h2f((Hb).y); m0 = fmaf(t.x, cw0[10], m0); m1 = fmaf(t.x, cw1[10], m1);    \
                     m0 = fmaf(t.y, cw0[11], m0); m1 = fmaf(t.y, cw1[11], m1);    \
    t = h2f((Hb).z); m0 = fmaf(t.x, cw0[12], m0); m1 = fmaf(t.x, cw1[12], m1);    \
                     m0 = fmaf(t.y, cw0[13], m0); m1 = fmaf(t.y, cw1[13], m1);    \
    t = h2f((Hb).w); m0 = fmaf(t.x, cw0[14], m0); m1 = fmaf(t.x, cw1[14], m1);    \
                     m0 = fmaf(t.y, cw0[15], m0); m1 = fmaf(t.y, cw1[15], m1);    \
    OUT0 = fmaxf(m0, 0.f); OUT1 = fmaxf(m1, 0.f);                                 \
} while (0)

// HOT (profiled): warp per dst node; 4 edges/iter, se prefetched one iter ahead;
// branchless flag tail; fp16 attr (L2-resident).
__global__ __launch_bounds__(128) void k_edge(int l) {
    int lane = threadIdx.x & 31;
    const float* C = d_C + l * 1024;
    float cw0[16], cw1[16];
#pragma unroll
    for (int k = 0; k < 16; k++) { cw0[k] = C[k * 64 + lane]; cw1[k] = C[k * 64 + lane + 32]; }
    float cb0 = d_cv[l * 64 + lane], cb1 = d_cv[l * 64 + lane + 32];
    float s0 = 0.f, q0 = 0.f, s1 = 0.f, q1 = 0.f;
    const float2* p2 = (const float2*)d_p;
    int gw = (blockIdx.x * blockDim.x + threadIdx.x) >> 5;
    int nw = (gridDim.x * blockDim.x) >> 5;
    for (int n = gw; n < NN; n += nw) {
        int deg = __ldg(&d_cnt[n]);
        deg = (deg > CAP) ? CAP : deg;
        const int2* bp = d_se + (size_t)n * CAP;
        float a0 = 0.f, a1 = 0.f;
        if (deg > 0) {
            int4 c0 = __ldg((const int4*)bp);        // edges 0,1
            int4 c1 = __ldg((const int4*)(bp + 2));  // edges 2,3
            for (int j = 0; j < deg; j += 4) {
                int4 n0 = __ldg((const int4*)(bp + j + 4));   // unconditional prefetch
                int4 n1 = __ldg((const int4*)(bp + j + 6));
                float2 pA = __ldg(&p2[(size_t)c0.x * 32 + lane]);
                float2 pB = __ldg(&p2[(size_t)c0.z * 32 + lane]);
                float2 pC = __ldg(&p2[(size_t)c1.x * 32 + lane]);
                float2 pD = __ldg(&p2[(size_t)c1.z * 32 + lane]);
                const uint4* aA = (const uint4*)(d_attrH + (size_t)c0.y * 16);
                const uint4* aB = (const uint4*)(d_attrH + (size_t)c0.w * 16);
                uint4 Aa = __ldg(aA), Ab = __ldg(aA + 1);
                uint4 Ba = __ldg(aB), Bb = __ldg(aB + 1);
                float fB = (j + 1 < deg) ? 1.f : 0.f;
                float fC = (j + 2 < deg) ? 1.f : 0.f;
                float fD = (j + 3 < deg) ? 1.f : 0.f;
                float mA0, mA1, mB0, mB1;
                MCHAIN(Aa, Ab, pA, mA0, mA1);
                MCHAIN(Ba, Bb, pB, mB0, mB1);
                const uint4* aC = (const uint4*)(d_attrH + (size_t)c1.y * 16);
                const uint4* aD = (const uint4*)(d_attrH + (size_t)c1.w * 16);
                uint4 Ca = __ldg(aC), Cb = __ldg(aC + 1);
                uint4 Da = __ldg(aD), Db = __ldg(aD + 1);
                float mC0, mC1, mD0, mD1;
                MCHAIN(Ca, Cb, pC, mC0, mC1);
                MCHAIN(Da, Db, pD, mD0, mD1);
                mB0 *= fB; mB1 *= fB;
                mC0 *= fC; mC1 *= fC;
                mD0 *= fD; mD1 *= fD;
                a0 += (mA0 + mB0) + (mC0 + mD0);
                a1 += (mA1 + mB1) + (mC1 + mD1);
                q0 = fmaf(mA0, mA0, q0); q1 = fmaf(mA1, mA1, q1);
                q0 = fmaf(mB0, mB0, q0); q1 = fmaf(mB1, mB1, q1);
                q0 = fmaf(mC0, mC0, q0); q1 = fmaf(mC1, mC1, q1);
                q0 = fmaf(mD0, mD0, q0); q1 = fmaf(mD1, mD1, q1);
                c0 = n0; c1 = n1;
            }
        }
        d_agg[n * 64 + lane]      = a0;
        d_agg[n * 64 + lane + 32] = a1;
        s0 += a0; s1 += a1;    // Σ_edges m == Σ_nodes agg
    }
    __shared__ float sS[64], sQ[64];
    int t = threadIdx.x;
    if (t < 64) { sS[t] = 0.f; sQ[t] = 0.f; }
    __syncthreads();
    atomicAdd(&sS[lane], s0);      atomicAdd(&sS[lane + 32], s1);
    atomicAdd(&sQ[lane], q0);      atomicAdd(&sQ[lane + 32], q1);
    __syncthreads();
    double* st = d_stats + l * 256;
    if (t < 64) { atomicAdd(&st[t], (double)sS[t]); atomicAdd(&st[64 + t], (double)sQ[t]); }
}

// u = relu( affine(h) @ Wu_h + affine(agg) @ Wu_a + b ); both BN affines computed
// inline from stats and folded into register weights.
__global__ __launch_bounds__(256) void k_update(const float* __restrict__ upd_W,
                                                const float* __restrict__ upd_b, int l,
                                                const float* __restrict__ msg_gamma,
                                                const float* __restrict__ msg_beta,
                                                const float* __restrict__ upd_gamma,
                                                const float* __restrict__ upd_beta) {
    __shared__ float smsc[64], smsh[64], spsc[64], spsh[64];
    if (threadIdx.x < 64) {
        int f = threadIdx.x;
        const double* st = d_stats + l * 256;          // message stats
        double mu  = st[f] / (double)NE;
        double var = st[64 + f] / (double)NE - mu * mu;
        float sc = msg_gamma[l * 64 + f] * rsqrtf((float)var + 1e-5f);
        smsc[f] = sc;
        smsh[f] = msg_beta[l * 64 + f] - (float)mu * sc;
    } else if (threadIdx.x < 128 && l > 0) {
        int f = threadIdx.x - 64;
        const double* st = d_stats + (l - 1) * 256 + 128;  // prev update stats
        double mu  = st[f] / (double)NN;
        double var = st[64 + f] / (double)NN - mu * mu;
        float sc = upd_gamma[(l - 1) * 64 + f] * rsqrtf((float)var + 1e-5f);
        spsc[f] = sc;
        spsh[f] = upd_beta[(l - 1) * 64 + f] - (float)mu * sc;
    }
    __syncthreads();
    const float* W = upd_W + l * 128 * 64;
    const float* in = (l == 0) ? d_h : d_u;
    int lane = threadIdx.x & 31;
    int sub  = (threadIdx.x >> 5) & 3;
    int slot = threadIdx.x >> 7;
    float w0[32], w1[32];
    float bias0 = 0.f, bias1 = 0.f;
#pragma unroll
    for (int kk = 0; kk < 32; kk++) {
        int k = sub * 32 + kk;
        float wa = W[k * 64 + lane], wb = W[k * 64 + lane + 32];
        if (sub < 2) {
            if (l > 0) {
                bias0 = fmaf(spsh[k], wa, bias0); bias1 = fmaf(spsh[k], wb, bias1);
                float s = spsc[k]; wa *= s; wb *= s;
            }
        } else {
            int ka = k - 64;
            bias0 = fmaf(smsh[ka], wa, bias0); bias1 = fmaf(smsh[ka], wb, bias1);  // ×deg later
            float s = smsc[ka]; wa *= s; wb *= s;
        }
        w0[kk] = wa; w1[kk] = wb;
    }
    float b0 = upd_b[l * 64 + lane], b1 = upd_b[l * 64 + lane + 32];
    __shared__ float2 red[2][4][32];
    float s0 = 0.f, q0 = 0.f, s1 = 0.f, q1 = 0.f;
    int stride = gridDim.x * 2;
    for (int nb = blockIdx.x * 2; nb < NN; nb += stride) {
        int n = nb + slot;
        bool act = (n < NN);
        float a0, a1;
        if (sub < 2) { a0 = bias0; a1 = bias1; }
        else {
            float degf = act ? (float)__ldg(&d_cnt[n]) : 0.f;
            a0 = degf * bias0; a1 = degf * bias1;
        }
        if (act) {
            float iv = (sub < 2) ? in[n * 64 + sub * 32 + lane]
                                 : d_agg[n * 64 + (sub - 2) * 32 + lane];
#pragma unroll
            for (int kk = 0; kk < 32; kk++) {
                float bc = __shfl_sync(0xffffffffu, iv, kk);
                a0 = fmaf(bc, w0[kk], a0); a1 = fmaf(bc, w1[kk], a1);
            }
        }
        if (sub) red[slot][sub][lane] = make_float2(a0, a1);
        __syncthreads();
        if (act && sub == 0) {
            float2 r1 = red[slot][1][lane], r2 = red[slot][2][lane], r3 = red[slot][3][lane];
            float v0 = a0 + r1.x + r2.x + r3.x + b0;
            float v1 = a1 + r1.y + r2.y + r3.y + b1;
            v0 = fmaxf(v0, 0.f); v1 = fmaxf(v1, 0.f);
            d_u[n * 64 + lane]      = v0;
            d_u[n * 64 + lane + 32] = v1;
            s0 += v0; q0 = fmaf(v0, v0, q0);
            s1 += v1; q1 = fmaf(v1, v1, q1);
        }
        __syncthreads();
    }
    __shared__ float sS[64], sQ[64];
    int t = threadIdx.x;
    if (t < 64) { sS[t] = 0.f; sQ[t] = 0.f; }
    __syncthreads();
    if (sub == 0) {
        atomicAdd(&sS[lane], s0);      atomicAdd(&sS[lane + 32], s1);
        atomicAdd(&sQ[lane], q0);      atomicAdd(&sQ[lane + 32], q1);
    }
    __syncthreads();
    double* st = d_stats + l * 256 + 128;
    if (t < 64) { atomicAdd(&st[t], (double)sS[t]); atomicAdd(&st[64 + t], (double)sQ[t]); }
}

// segmented pool over sorted batch (raw u + counts); also self-cleans d_cnt
#define PL_BLOCKS 128
__global__ __launch_bounds__(256) void k_pool(const int* __restrict__ batch) {
    for (int i = blockIdx.x * blockDim.x + threadIdx.x; i < NN; i += PL_BLOCKS * 256)
        d_cnt[i] = 0;
    int lane = threadIdx.x & 31;
    int w = (blockIdx.x * 256 + threadIdx.x) >> 5;      // 1024 warps
    const int chunk = (NN + 1023) / 1024;               // 98
    int s = w * chunk, e = s + chunk;
    if (e > NN) e = NN;
    if (s >= NN) return;
    int curg = __ldg(&batch[s]);
    float A0 = 0.f, A1 = 0.f; int cnt = 0;
    for (int n = s; n < e; n++) {
        int g = __ldg(&batch[n]);
        if (g != curg) {
            atomicAdd(&d_gpool[curg * 64 + lane],      A0);
            atomicAdd(&d_gpool[curg * 64 + lane + 32], A1);
            if (lane == 0) atomicAdd(&d_gcnt[curg], cnt);
            curg = g; A0 = 0.f; A1 = 0.f; cnt = 0;
        }
        A0 += d_u[n * 64 + lane];
        A1 += d_u[n * 64 + lane + 32];
        cnt++;
    }
    atomicAdd(&d_gpool[curg * 64 + lane],      A0);
    atomicAdd(&d_gpool[curg * 64 + lane + 32], A1);
    if (lane == 0) atomicAdd(&d_gcnt[curg], cnt);
}

// readout: final BN affine computed inline from stats; self-cleans pool/cnt
__global__ void k_readout(const float* __restrict__ r1_W, const float* __restrict__ r1_b,
                          const float* __restrict__ r2_W, const float* __restrict__ r2_b,
                          const float* __restrict__ upd_gamma,
                          const float* __restrict__ upd_beta,
                          float* __restrict__ out) {
    int gid = blockIdx.x, f = threadIdx.x;
    __shared__ float gv[64];
    const double* st = d_stats + 2 * 256 + 128;
    double mu  = st[f] / (double)NN;
    double var = st[64 + f] / (double)NN - mu * mu;
    float sc = upd_gamma[2 * 64 + f] * rsqrtf((float)var + 1e-5f);
    float sh = upd_beta[2 * 64 + f] - (float)mu * sc;
    float cntf = (float)d_gcnt[gid];
    gv[f] = fmaf(sc, d_gpool[gid * 64 + f], cntf * sh);
    __syncthreads();
    d_gpool[gid * 64 + f] = 0.f;
    if (f == 0) d_gcnt[gid] = 0;
    float acc = r1_b[f];
    for (int k = 0; k < 64; k++)
        acc = fmaf(gv[k], r1_W[k * 64 + f], acc);
    acc = fmaxf(acc, 0.f);
    float val = acc * r2_W[f];
    __shared__ float sh2[64];
    sh2[f] = val;
    __syncthreads();
    if (f < 32) sh2[f] += sh2[f + 32];
    __syncthreads();
    if (f < 16) sh2[f] += sh2[f + 16];
    __syncthreads();
    if (f < 8) sh2[f] += sh2[f + 8];
    __syncthreads();
    if (f < 4) sh2[f] += sh2[f + 4];
    __syncthreads();
    if (f < 2) sh2[f] += sh2[f + 2];
    __syncthreads();
    if (f == 0) out[gid] = sh2[0] + sh2[1] + r2_b[0];
}

extern "C" void kernel_launch(void* const* d_in, const int* in_sizes, int n_in,
                              void* d_out, int out_size) {
    const float* x         = (const float*)d_in[0];
    const float* edge_attr = (const float*)d_in[1];
    const int*   edge_idx  = (const int*)d_in[2];
    const int*   batch     = (const int*)d_in[3];
    const float* node_W    = (const float*)d_in[4];
    const float* node_b    = (const float*)d_in[5];
    const float* edge_W    = (const float*)d_in[6];
    const float* edge_b    = (const float*)d_in[7];
    const float* msg_W     = (const float*)d_in[8];
    const float* msg_b     = (const float*)d_in[9];
    const float* msg_gamma = (const float*)d_in[10];
    const float* msg_beta  = (const float*)d_in[11];
    const float* upd_W     = (const float*)d_in[12];
    const float* upd_b     = (const float*)d_in[13];
    const float* upd_gamma = (const float*)d_in[14];
    const float* upd_beta  = (const float*)d_in[15];
    const float* r1_W      = (const float*)d_in[16];
    const float* r1_b      = (const float*)d_in[17];
    const float* r2_W      = (const float*)d_in[18];
    const float* r2_b      = (const float*)d_in[19];
    float* out = (float*)d_out;

    const int* src = edge_idx;
    const int* dst = edge_idx + NE;

    k_scatter<<<2048, 256>>>(src, dst, edge_attr);                 // 0
    k_embed<<<EM_BLOCKS + 1, 256>>>(x, node_W, node_b,
                                    edge_W, edge_b, msg_W, msg_b); // 1
    for (int l = 0; l < 3; l++) {
        k_p<<<1024, 256>>>(msg_W, l, upd_gamma, upd_beta);         // 2 (l=0)
        k_edge<<<4096, 128>>>(l);                                  // 3 (l=0) <- profiled
        k_update<<<1024, 256>>>(upd_W, upd_b, l, msg_gamma, msg_beta,
                                upd_gamma, upd_beta);
    }
    k_pool<<<PL_BLOCKS, 256>>>(batch);
    k_readout<<<NG, 64>>>(r1_W, r1_b, r2_W, r2_b, upd_gamma, upd_beta, out);
}

// round 13
// speedup vs baseline: 1.0657x; 1.0657x over previous
#include <cuda_runtime.h>
#include <cuda_fp16.h>

#define NN 100000
#define NE 1600000
#define NG 1000
#define CAP 64

// ---------------- scratch (device globals; zero-initialized at load) ----------------
__device__ float  d_h[NN * 64];
__device__ float  d_p[NN * 64];     // float2-interleaved: ((float2*)d_p)[n*32+lane] = {f, f+32}
__device__ float  d_u[NN * 64];
__device__ float  d_agg[NN * 64];
__device__ __half d_attrH[NE * 16]; // fp16 copy of edge_attr (row-major, 32B/row)
__device__ float  d_gpool[NG * 64];
__device__ int    d_gcnt[NG];
__device__ int    d_cnt[NN];          // zero-init; re-zeroed by k_pool each run
__device__ int2   d_se[NN * CAP + 8]; // per-dst bucket of (src, eid); pad for ahead-loads
__device__ float  d_C[3 * 16 * 64];
__device__ float  d_cv[3 * 64];
__device__ double d_stats[3 * 256];   // cleaned by k_scatter each run

__device__ __forceinline__ unsigned pkh2(float lo, float hi) {
    __half2 h = __floats2half2_rn(lo, hi);
    return *reinterpret_cast<unsigned*>(&h);
}
__device__ __forceinline__ float2 h2f(unsigned u) {
    return __half22float2(*reinterpret_cast<__half2*>(&u));
}

// launch 0: bucket scatter + fp16 attr conversion (single fused pass) + stats clean
__global__ __launch_bounds__(256) void k_scatter(const int* __restrict__ src,
                                                 const int* __restrict__ dst,
                                                 const float* __restrict__ attr) {
    int tid0 = blockIdx.x * blockDim.x + threadIdx.x;
    if (tid0 < 3 * 256) d_stats[tid0] = 0.0;
    int stride = gridDim.x * blockDim.x;
    for (int i = tid0; i < NE; i += stride) {
        int d = dst[i];
        int pos = atomicAdd(&d_cnt[d], 1);
        if (pos < CAP) d_se[d * CAP + pos] = make_int2(src[i], i);
        const float4* a4 = (const float4*)(attr + (size_t)i * 16);
        float4 v0 = a4[0], v1 = a4[1], v2 = a4[2], v3 = a4[3];
        uint4 o0, o1;
        o0.x = pkh2(v0.x, v0.y); o0.y = pkh2(v0.z, v0.w);
        o0.z = pkh2(v1.x, v1.y); o0.w = pkh2(v1.z, v1.w);
        o1.x = pkh2(v2.x, v2.y); o1.y = pkh2(v2.z, v2.w);
        o1.z = pkh2(v3.x, v3.y); o1.w = pkh2(v3.z, v3.w);
        uint4* hp = (uint4*)(d_attrH + (size_t)i * 16);
        hp[0] = o0; hp[1] = o1;
    }
}

// launch 1: embed (warp per node, weights in regs) + composite-C (last block)
#define EM_BLOCKS 512
__global__ __launch_bounds__(256) void k_embed(const float* __restrict__ x,
                                               const float* __restrict__ node_W,
                                               const float* __restrict__ node_b,
                                               const float* __restrict__ edge_W,
                                               const float* __restrict__ edge_b,
                                               const float* __restrict__ msg_W,
                                               const float* __restrict__ msg_b) {
    int b = blockIdx.x;
    if (b < EM_BLOCKS) {
        int lane = threadIdx.x & 31;
        float w0[32], w1[32];
#pragma unroll
        for (int k = 0; k < 32; k++) { w0[k] = node_W[k * 64 + lane]; w1[k] = node_W[k * 64 + lane + 32]; }
        float b0 = node_b[lane], b1 = node_b[lane + 32];
        int gw = (b * 256 + threadIdx.x) >> 5;
        int nw = (EM_BLOCKS * 256) >> 5;
        for (int n = gw; n < NN; n += nw) {
            float xv = x[n * 32 + lane];
            float a0 = b0, a1 = b1;
#pragma unroll
            for (int k = 0; k < 32; k++) {
                float bc = __shfl_sync(0xffffffffu, xv, k);
                a0 = fmaf(bc, w0[k], a0); a1 = fmaf(bc, w1[k], a1);
            }
            d_h[n * 64 + lane] = a0; d_h[n * 64 + lane + 32] = a1;
        }
    } else {
        int t = threadIdx.x;
        if (t < 192) {
            int l = t >> 6, f = t & 63;
            const float* Wm = msg_W + l * 96 * 64 + 64 * 64;
            for (int kk = 0; kk < 16; kk++) {
                float s = 0.f;
                for (int j = 0; j < 32; j++) s = fmaf(edge_W[kk * 32 + j], Wm[j * 64 + f], s);
                d_C[l * 1024 + kk * 64 + f] = s;
            }
            float cv = msg_b[l * 64 + f];
            for (int j = 0; j < 32; j++) cv = fmaf(edge_b[j], Wm[j * 64 + f], cv);
            d_cv[l * 64 + f] = cv;
        }
    }
}

// p = in @ msg_W[l][0:64,:] (prev BN affine from stats, folded); double-buffered
// reduction smem -> ONE __syncthreads per iteration.
__global__ __launch_bounds__(256) void k_p(const float* __restrict__ msg_W, int l,
                                           const float* __restrict__ upd_gamma,
                                           const float* __restrict__ upd_beta) {
    __shared__ float ssc[64], ssh[64];
    if (l > 0 && threadIdx.x < 64) {
        int f = threadIdx.x;
        const double* st = d_stats + (l - 1) * 256 + 128;
        double mu  = st[f] / (double)NN;
        double var = st[64 + f] / (double)NN - mu * mu;
        float sc = upd_gamma[(l - 1) * 64 + f] * rsqrtf((float)var + 1e-5f);
        ssc[f] = sc;
        ssh[f] = upd_beta[(l - 1) * 64 + f] - (float)mu * sc;
    }
    __syncthreads();
    const float* W = msg_W + l * 96 * 64;
    const float* in = (l == 0) ? d_h : d_u;
    int lane = threadIdx.x & 31;
    int half = (threadIdx.x >> 5) & 1;
    int pib  = threadIdx.x >> 6;
    float w0[32], w1[32];
    float bias0 = 0.f, bias1 = 0.f;
#pragma unroll
    for (int kk = 0; kk < 32; kk++) {
        int k = half * 32 + kk;
        float wa = W[k * 64 + lane], wb = W[k * 64 + lane + 32];
        if (l > 0) {
            bias0 = fmaf(ssh[k], wa, bias0); bias1 = fmaf(ssh[k], wb, bias1);
            float s = ssc[k]; wa *= s; wb *= s;
        }
        w0[kk] = wa; w1[kk] = wb;
    }
    __shared__ float2 red[2][4][32];
    float2* p2 = (float2*)d_p;
    int stride = gridDim.x * 4;
    int buf = 0;
    for (int nb = blockIdx.x * 4; nb < NN; nb += stride) {
        int n = nb + pib;
        bool act = (n < NN);
        float a0 = bias0, a1 = bias1;
        if (act) {
            float hv = in[n * 64 + half * 32 + lane];
#pragma unroll
            for (int kk = 0; kk < 32; kk++) {
                float bc = __shfl_sync(0xffffffffu, hv, kk);
                a0 = fmaf(bc, w0[kk], a0); a1 = fmaf(bc, w1[kk], a1);
            }
        }
        if (half == 1) red[buf][pib][lane] = make_float2(a0, a1);
        __syncthreads();
        if (act && half == 0) {
            float2 o = red[buf][pib][lane];
            p2[(size_t)n * 32 + lane] = make_float2(a0 + o.x, a1 + o.y);
        }
        buf ^= 1;
    }
}

// HOT (profiled): warp per dst node; R11-exact 2-edge interleaved body;
// se prefetched one iter ahead; fp16 attr (L2-resident); branchless odd tail.
__global__ __launch_bounds__(128) void k_edge(int l) {
    int lane = threadIdx.x & 31;
    const float* C = d_C + l * 1024;
    float cw0[16], cw1[16];
#pragma unroll
    for (int k = 0; k < 16; k++) { cw0[k] = C[k * 64 + lane]; cw1[k] = C[k * 64 + lane + 32]; }
    float cb0 = d_cv[l * 64 + lane], cb1 = d_cv[l * 64 + lane + 32];
    float s0 = 0.f, q0 = 0.f, s1 = 0.f, q1 = 0.f;
    const float2* p2 = (const float2*)d_p;
    int gw = (blockIdx.x * blockDim.x + threadIdx.x) >> 5;
    int nw = (gridDim.x * blockDim.x) >> 5;
    for (int n = gw; n < NN; n += nw) {
        int deg = __ldg(&d_cnt[n]);
        deg = (deg > CAP) ? CAP : deg;
        const int2* bp = d_se + (size_t)n * CAP;
        float a0 = 0.f, a1 = 0.f;
        if (deg > 0) {
            int4 cur = __ldg((const int4*)bp);   // edges 0,1 (16B aligned)
            for (int j = 0; j < deg; j += 2) {
                int4 nxt = __ldg((const int4*)(bp + j + 2));   // unconditional ahead-load
                float2 pa = __ldg(&p2[(size_t)cur.x * 32 + lane]);
                float2 pb = __ldg(&p2[(size_t)cur.z * 32 + lane]);
                const uint4* apA = (const uint4*)(d_attrH + (size_t)cur.y * 16);
                const uint4* apB = (const uint4*)(d_attrH + (size_t)cur.w * 16);
                uint4 Aa = __ldg(apA), Ab = __ldg(apA + 1);
                uint4 Ba = __ldg(apB), Bb = __ldg(apB + 1);
                float flagB = (j + 1 < deg) ? 1.f : 0.f;
                float2 A0 = h2f(Aa.x), A1 = h2f(Aa.y), A2 = h2f(Aa.z), A3 = h2f(Aa.w);
                float2 A4 = h2f(Ab.x), A5 = h2f(Ab.y), A6 = h2f(Ab.z), A7 = h2f(Ab.w);
                float2 B0 = h2f(Ba.x), B1 = h2f(Ba.y), B2 = h2f(Ba.z), B3 = h2f(Ba.w);
                float2 B4 = h2f(Bb.x), B5 = h2f(Bb.y), B6 = h2f(Bb.z), B7 = h2f(Bb.w);
                float ma0 = pa.x + cb0, ma1 = pa.y + cb1;
                float mb0 = pb.x + cb0, mb1 = pb.y + cb1;
                ma0 = fmaf(A0.x, cw0[0], ma0);  ma1 = fmaf(A0.x, cw1[0], ma1);
                mb0 = fmaf(B0.x, cw0[0], mb0);  mb1 = fmaf(B0.x, cw1[0], mb1);
                ma0 = fmaf(A0.y, cw0[1], ma0);  ma1 = fmaf(A0.y, cw1[1], ma1);
                mb0 = fmaf(B0.y, cw0[1], mb0);  mb1 = fmaf(B0.y, cw1[1], mb1);
                ma0 = fmaf(A1.x, cw0[2], ma0);  ma1 = fmaf(A1.x, cw1[2], ma1);
                mb0 = fmaf(B1.x, cw0[2], mb0);  mb1 = fmaf(B1.x, cw1[2], mb1);
                ma0 = fmaf(A1.y, cw0[3], ma0);  ma1 = fmaf(A1.y, cw1[3], ma1);
                mb0 = fmaf(B1.y, cw0[3], mb0);  mb1 = fmaf(B1.y, cw1[3], mb1);
                ma0 = fmaf(A2.x, cw0[4], ma0);  ma1 = fmaf(A2.x, cw1[4], ma1);
                mb0 = fmaf(B2.x, cw0[4], mb0);  mb1 = fmaf(B2.x, cw1[4], mb1);
                ma0 = fmaf(A2.y, cw0[5], ma0);  ma1 = fmaf(A2.y, cw1[5], ma1);
                mb0 = fmaf(B2.y, cw0[5], mb0);  mb1 = fmaf(B2.y, cw1[5], mb1);
                ma0 = fmaf(A3.x, cw0[6], ma0);  ma1 = fmaf(A3.x, cw1[6], ma1);
                mb0 = fmaf(B3.x, cw0[6], mb0);  mb1 = fmaf(B3.x, cw1[6], mb1);
                ma0 = fmaf(A3.y, cw0[7], ma0);  ma1 = fmaf(A3.y, cw1[7], ma1);
                mb0 = fmaf(B3.y, cw0[7], mb0);  mb1 = fmaf(B3.y, cw1[7], mb1);
                ma0 = fmaf(A4.x, cw0[8], ma0);  ma1 = fmaf(A4.x, cw1[8], ma1);
                mb0 = fmaf(B4.x, cw0[8], mb0);  mb1 = fmaf(B4.x, cw1[8], mb1);
                ma0 = fmaf(A4.y, cw0[9], ma0);  ma1 = fmaf(A4.y, cw1[9], ma1);
                mb0 = fmaf(B4.y, cw0[9], mb0);  mb1 = fmaf(B4.y, cw1[9], mb1);
                ma0 = fmaf(A5.x, cw0[10], ma0); ma1 = fmaf(A5.x, cw1[10], ma1);
                mb0 = fmaf(B5.x, cw0[10], mb0); mb1 = fmaf(B5.x, cw1[10], mb1);
                ma0 = fmaf(A5.y, cw0[11], ma0); ma1 = fmaf(A5.y, cw1[11], ma1);
                mb0 = fmaf(B5.y, cw0[11], mb0); mb1 = fmaf(B5.y, cw1[11], mb1);
                ma0 = fmaf(A6.x, cw0[12], ma0); ma1 = fmaf(A6.x, cw1[12], ma1);
                mb0 = fmaf(B6.x, cw0[12], mb0); mb1 = fmaf(B6.x, cw1[12], mb1);
                ma0 = fmaf(A6.y, cw0[13], ma0); ma1 = fmaf(A6.y, cw1[13], ma1);
                mb0 = fmaf(B6.y, cw0[13], mb0); mb1 = fmaf(B6.y, cw1[13], mb1);
                ma0 = fmaf(A7.x, cw0[14], ma0); ma1 = fmaf(A7.x, cw1[14], ma1);
                mb0 = fmaf(B7.x, cw0[14], mb0); mb1 = fmaf(B7.x, cw1[14], mb1);
                ma0 = fmaf(A7.y, cw0[15], ma0); ma1 = fmaf(A7.y, cw1[15], ma1);
                mb0 = fmaf(B7.y, cw0[15], mb0); mb1 = fmaf(B7.y, cw1[15], mb1);
                ma0 = fmaxf(ma0, 0.f); ma1 = fmaxf(ma1, 0.f);
                mb0 = fmaxf(mb0, 0.f) * flagB; mb1 = fmaxf(mb1, 0.f) * flagB;
                a0 += ma0 + mb0; a1 += ma1 + mb1;
                q0 = fmaf(ma0, ma0, q0); q1 = fmaf(ma1, ma1, q1);
                q0 = fmaf(mb0, mb0, q0); q1 = fmaf(mb1, mb1, q1);
                cur = nxt;
            }
        }
        d_agg[n * 64 + lane]      = a0;
        d_agg[n * 64 + lane + 32] = a1;
        s0 += a0; s1 += a1;    // Σ_edges m == Σ_nodes agg
    }
    __shared__ float sS[64], sQ[64];
    int t = threadIdx.x;
    if (t < 64) { sS[t] = 0.f; sQ[t] = 0.f; }
    __syncthreads();
    atomicAdd(&sS[lane], s0);      atomicAdd(&sS[lane + 32], s1);
    atomicAdd(&sQ[lane], q0);      atomicAdd(&sQ[lane + 32], q1);
    __syncthreads();
    double* st = d_stats + l * 256;
    if (t < 64) { atomicAdd(&st[t], (double)sS[t]); atomicAdd(&st[64 + t], (double)sQ[t]); }
}

// u = relu( affine(h) @ Wu_h + affine(agg) @ Wu_a + b ); BN affines inline from
// stats; double-buffered reduction smem -> ONE __syncthreads per iteration.
__global__ __launch_bounds__(256) void k_update(const float* __restrict__ upd_W,
                                                const float* __restrict__ upd_b, int l,
                                                const float* __restrict__ msg_gamma,
                                                const float* __restrict__ msg_beta,
                                                const float* __restrict__ upd_gamma,
                                                const float* __restrict__ upd_beta) {
    __shared__ float smsc[64], smsh[64], spsc[64], spsh[64];
    if (threadIdx.x < 64) {
        int f = threadIdx.x;
        const double* st = d_stats + l * 256;          // message stats
        double mu  = st[f] / (double)NE;
        double var = st[64 + f] / (double)NE - mu * mu;
        float sc = msg_gamma[l * 64 + f] * rsqrtf((float)var + 1e-5f);
        smsc[f] = sc;
        smsh[f] = msg_beta[l * 64 + f] - (float)mu * sc;
    } else if (threadIdx.x < 128 && l > 0) {
        int f = threadIdx.x - 64;
        const double* st = d_stats + (l - 1) * 256 + 128;  // prev update stats
        double mu  = st[f] / (double)NN;
        double var = st[64 + f] / (double)NN - mu * mu;
        float sc = upd_gamma[(l - 1) * 64 + f] * rsqrtf((float)var + 1e-5f);
        spsc[f] = sc;
        spsh[f] = upd_beta[(l - 1) * 64 + f] - (float)mu * sc;
    }
    __syncthreads();
    const float* W = upd_W + l * 128 * 64;
    const float* in = (l == 0) ? d_h : d_u;
    int lane = threadIdx.x & 31;
    int sub  = (threadIdx.x >> 5) & 3;
    int slot = threadIdx.x >> 7;
    float w0[32], w1[32];
    float bias0 = 0.f, bias1 = 0.f;
#pragma unroll
    for (int kk = 0; kk < 32; kk++) {
        int k = sub * 32 + kk;
        float wa = W[k * 64 + lane], wb = W[k * 64 + lane + 32];
        if (sub < 2) {
            if (l > 0) {
                bias0 = fmaf(spsh[k], wa, bias0); bias1 = fmaf(spsh[k], wb, bias1);
                float s = spsc[k]; wa *= s; wb *= s;
            }
        } else {
            int ka = k - 64;
            bias0 = fmaf(smsh[ka], wa, bias0); bias1 = fmaf(smsh[ka], wb, bias1);  // ×deg later
            float s = smsc[ka]; wa *= s; wb *= s;
        }
        w0[kk] = wa; w1[kk] = wb;
    }
    float b0 = upd_b[l * 64 + lane], b1 = upd_b[l * 64 + lane + 32];
    __shared__ float2 red[2][2][4][32];   // [buf][slot][sub][lane]
    float s0 = 0.f, q0 = 0.f, s1 = 0.f, q1 = 0.f;
    int stride = gridDim.x * 2;
    int buf = 0;
    for (int nb = blockIdx.x * 2; nb < NN; nb += stride) {
        int n = nb + slot;
        bool act = (n < NN);
        float a0, a1;
        if (sub < 2) { a0 = bias0; a1 = bias1; }
        else {
            float degf = act ? (float)__ldg(&d_cnt[n]) : 0.f;
            a0 = degf * bias0; a1 = degf * bias1;
        }
        if (act) {
            float iv = (sub < 2) ? in[n * 64 + sub * 32 + lane]
                                 : d_agg[n * 64 + (sub - 2) * 32 + lane];
#pragma unroll
            for (int kk = 0; kk < 32; kk++) {
                float bc = __shfl_sync(0xffffffffu, iv, kk);
                a0 = fmaf(bc, w0[kk], a0); a1 = fmaf(bc, w1[kk], a1);
            }
        }
        if (sub) red[buf][slot][sub][lane] = make_float2(a0, a1);
        __syncthreads();
        if (act && sub == 0) {
            float2 r1 = red[buf][slot][1][lane], r2 = red[buf][slot][2][lane],
                   r3 = red[buf][slot][3][lane];
            float v0 = a0 + r1.x + r2.x + r3.x + b0;
            float v1 = a1 + r1.y + r2.y + r3.y + b1;
            v0 = fmaxf(v0, 0.f); v1 = fmaxf(v1, 0.f);
            d_u[n * 64 + lane]      = v0;
            d_u[n * 64 + lane + 32] = v1;
            s0 += v0; q0 = fmaf(v0, v0, q0);
            s1 += v1; q1 = fmaf(v1, v1, q1);
        }
        buf ^= 1;
    }
    __shared__ float sS[64], sQ[64];
    int t = threadIdx.x;
    if (t < 64) { sS[t] = 0.f; sQ[t] = 0.f; }
    __syncthreads();
    if (sub == 0) {
        atomicAdd(&sS[lane], s0);      atomicAdd(&sS[lane + 32], s1);
        atomicAdd(&sQ[lane], q0);      atomicAdd(&sQ[lane + 32], q1);
    }
    __syncthreads();
    double* st = d_stats + l * 256 + 128;
    if (t < 64) { atomicAdd(&st[t], (double)sS[t]); atomicAdd(&st[64 + t], (double)sQ[t]); }
}

// segmented pool over sorted batch (raw u + counts); also self-cleans d_cnt
#define PL_BLOCKS 128
__global__ __launch_bounds__(256) void k_pool(const int* __restrict__ batch) {
    for (int i = blockIdx.x * blockDim.x + threadIdx.x; i < NN; i += PL_BLOCKS * 256)
        d_cnt[i] = 0;
    int lane = threadIdx.x & 31;
    int w = (blockIdx.x * 256 + threadIdx.x) >> 5;      // 1024 warps
    const int chunk = (NN + 1023) / 1024;               // 98
    int s = w * chunk, e = s + chunk;
    if (e > NN) e = NN;
    if (s >= NN) return;
    int curg = __ldg(&batch[s]);
    float A0 = 0.f, A1 = 0.f; int cnt = 0;
    for (int n = s; n < e; n++) {
        int g = __ldg(&batch[n]);
        if (g != curg) {
            atomicAdd(&d_gpool[curg * 64 + lane],      A0);
            atomicAdd(&d_gpool[curg * 64 + lane + 32], A1);
            if (lane == 0) atomicAdd(&d_gcnt[curg], cnt);
            curg = g; A0 = 0.f; A1 = 0.f; cnt = 0;
        }
        A0 += d_u[n * 64 + lane];
        A1 += d_u[n * 64 + lane + 32];
        cnt++;
    }
    atomicAdd(&d_gpool[curg * 64 + lane],      A0);
    atomicAdd(&d_gpool[curg * 64 + lane + 32], A1);
    if (lane == 0) atomicAdd(&d_gcnt[curg], cnt);
}

// readout: final BN affine inline from stats; self-cleans pool/cnt
__global__ void k_readout(const float* __restrict__ r1_W, const float* __restrict__ r1_b,
                          const float* __restrict__ r2_W, const float* __restrict__ r2_b,
                          const float* __restrict__ upd_gamma,
                          const float* __restrict__ upd_beta,
                          float* __restrict__ out) {
    int gid = blockIdx.x, f = threadIdx.x;
    __shared__ float gv[64];
    const double* st = d_stats + 2 * 256 + 128;
    double mu  = st[f] / (double)NN;
    double var = st[64 + f] / (double)NN - mu * mu;
    float sc = upd_gamma[2 * 64 + f] * rsqrtf((float)var + 1e-5f);
    float sh = upd_beta[2 * 64 + f] - (float)mu * sc;
    float cntf = (float)d_gcnt[gid];
    gv[f] = fmaf(sc, d_gpool[gid * 64 + f], cntf * sh);
    __syncthreads();
    d_gpool[gid * 64 + f] = 0.f;
    if (f == 0) d_gcnt[gid] = 0;
    float acc = r1_b[f];
    for (int k = 0; k < 64; k++)
        acc = fmaf(gv[k], r1_W[k * 64 + f], acc);
    acc = fmaxf(acc, 0.f);
    float val = acc * r2_W[f];
    __shared__ float sh2[64];
    sh2[f] = val;
    __syncthreads();
    if (f < 32) sh2[f] += sh2[f + 32];
    __syncthreads();
    if (f < 16) sh2[f] += sh2[f + 16];
    __syncthreads();
    if (f < 8) sh2[f] += sh2[f + 8];
    __syncthreads();
    if (f < 4) sh2[f] += sh2[f + 4];
    __syncthreads();
    if (f < 2) sh2[f] += sh2[f + 2];
    __syncthreads();
    if (f == 0) out[gid] = sh2[0] + sh2[1] + r2_b[0];
}

extern "C" void kernel_launch(void* const* d_in, const int* in_sizes, int n_in,
                              void* d_out, int out_size) {
    const float* x         = (const float*)d_in[0];
    const float* edge_attr = (const float*)d_in[1];
    const int*   edge_idx  = (const int*)d_in[2];
    const int*   batch     = (const int*)d_in[3];
    const float* node_W    = (const float*)d_in[4];
    const float* node_b    = (const float*)d_in[5];
    const float* edge_W    = (const float*)d_in[6];
    const float* edge_b    = (const float*)d_in[7];
    const float* msg_W     = (const float*)d_in[8];
    const float* msg_b     = (const float*)d_in[9];
    const float* msg_gamma = (const float*)d_in[10];
    const float* msg_beta  = (const float*)d_in[11];
    const float* upd_W     = (const float*)d_in[12];
    const float* upd_b     = (const float*)d_in[13];
    const float* upd_gamma = (const float*)d_in[14];
    const float* upd_beta  = (const float*)d_in[15];
    const float* r1_W      = (const float*)d_in[16];
    const float* r1_b      = (const float*)d_in[17];
    const float* r2_W      = (const float*)d_in[18];
    const float* r2_b      = (const float*)d_in[19];
    float* out = (float*)d_out;

    const int* src = edge_idx;
    const int* dst = edge_idx + NE;

    k_scatter<<<2048, 256>>>(src, dst, edge_attr);                 // 0
    k_embed<<<EM_BLOCKS + 1, 256>>>(x, node_W, node_b,
                                    edge_W, edge_b, msg_W, msg_b); // 1
    for (int l = 0; l < 3; l++) {
        k_p<<<1024, 256>>>(msg_W, l, upd_gamma, upd_beta);         // 2 (l=0)
        k_edge<<<4096, 128>>>(l);                                  // 3 (l=0) <- profiled
        k_update<<<1024, 256>>>(upd_W, upd_b, l, msg_gamma, msg_beta,
                                upd_gamma, upd_beta);
    }
    k_pool<<<PL_BLOCKS, 256>>>(batch);
    k_readout<<<NG, 64>>>(r1_W, r1_b, r2_W, r2_b, upd_gamma, upd_beta, out);
}

// round 14
// speedup vs baseline: 1.2126x; 1.1378x over previous
#include <cuda_runtime.h>
#include <cuda_fp16.h>

#define NN 100000
#define NE 1600000
#define NG 1000
#define CAP 64

// ---------------- scratch (device globals; zero-initialized at load) ----------------
__device__ float  d_h[NN * 64];
__device__ float  d_p[NN * 64];     // float2-interleaved
__device__ float  d_u[NN * 64];
__device__ float  d_agg[NN * 64];
__device__ __half d_attrH[NE * 16];
__device__ float  d_gpool[NG * 64];
__device__ int    d_gcnt[NG];
__device__ int    d_cnt[NN];          // zero-init; re-zeroed by k_pool each run
__device__ int2   d_se[NN * CAP + 8];
__device__ float  d_C[3 * 16 * 64];
__device__ float  d_cv[3 * 64];
__device__ double d_stats[3 * 256];   // cleaned by k_scatter each run

__device__ __forceinline__ unsigned pkh2(float lo, float hi) {
    __half2 h = __floats2half2_rn(lo, hi);
    return *reinterpret_cast<unsigned*>(&h);
}
__device__ __forceinline__ float2 h2f(unsigned u) {
    return __half22float2(*reinterpret_cast<__half2*>(&u));
}

// launch 0: bucket scatter + fp16 attr conversion (fused) + stats clean
__global__ __launch_bounds__(256) void k_scatter(const int* __restrict__ src,
                                                 const int* __restrict__ dst,
                                                 const float* __restrict__ attr) {
    int tid0 = blockIdx.x * blockDim.x + threadIdx.x;
    if (tid0 < 3 * 256) d_stats[tid0] = 0.0;
    int stride = gridDim.x * blockDim.x;
    for (int i = tid0; i < NE; i += stride) {
        int d = dst[i];
        int pos = atomicAdd(&d_cnt[d], 1);
        if (pos < CAP) d_se[d * CAP + pos] = make_int2(src[i], i);
        const float4* a4 = (const float4*)(attr + (size_t)i * 16);
        float4 v0 = a4[0], v1 = a4[1], v2 = a4[2], v3 = a4[3];
        uint4 o0, o1;
        o0.x = pkh2(v0.x, v0.y); o0.y = pkh2(v0.z, v0.w);
        o0.z = pkh2(v1.x, v1.y); o0.w = pkh2(v1.z, v1.w);
        o1.x = pkh2(v2.x, v2.y); o1.y = pkh2(v2.z, v2.w);
        o1.z = pkh2(v3.x, v3.y); o1.w = pkh2(v3.z, v3.w);
        uint4* hp = (uint4*)(d_attrH + (size_t)i * 16);
        hp[0] = o0; hp[1] = o1;
    }
}

// launch 1: embed + composite-C
#define EM_BLOCKS 512
__global__ __launch_bounds__(256) void k_embed(const float* __restrict__ x,
                                               const float* __restrict__ node_W,
                                               const float* __restrict__ node_b,
                                               const float* __restrict__ edge_W,
                                               const float* __restrict__ edge_b,
                                               const float* __restrict__ msg_W,
                                               const float* __restrict__ msg_b) {
    int b = blockIdx.x;
    if (b < EM_BLOCKS) {
        int lane = threadIdx.x & 31;
        float w0[32], w1[32];
#pragma unroll
        for (int k = 0; k < 32; k++) { w0[k] = node_W[k * 64 + lane]; w1[k] = node_W[k * 64 + lane + 32]; }
        float b0 = node_b[lane], b1 = node_b[lane + 32];
        int gw = (b * 256 + threadIdx.x) >> 5;
        int nw = (EM_BLOCKS * 256) >> 5;
        for (int n = gw; n < NN; n += nw) {
            float xv = x[n * 32 + lane];
            float a0 = b0, a1 = b1;
#pragma unroll
            for (int k = 0; k < 32; k++) {
                float bc = __shfl_sync(0xffffffffu, xv, k);
                a0 = fmaf(bc, w0[k], a0); a1 = fmaf(bc, w1[k], a1);
            }
            d_h[n * 64 + lane] = a0; d_h[n * 64 + lane + 32] = a1;
        }
    } else {
        int t = threadIdx.x;
        if (t < 192) {
            int l = t >> 6, f = t & 63;
            const float* Wm = msg_W + l * 96 * 64 + 64 * 64;
            for (int kk = 0; kk < 16; kk++) {
                float s = 0.f;
                for (int j = 0; j < 32; j++) s = fmaf(edge_W[kk * 32 + j], Wm[j * 64 + f], s);
                d_C[l * 1024 + kk * 64 + f] = s;
            }
            float cv = msg_b[l * 64 + f];
            for (int j = 0; j < 32; j++) cv = fmaf(edge_b[j], Wm[j * 64 + f], cv);
            d_cv[l * 64 + f] = cv;
        }
    }
}

// p = in @ msg_W[l][0:64,:]; 4 nodes per warp-pair per iteration (MLP 4, sync/4)
__global__ __launch_bounds__(256) void k_p(const float* __restrict__ msg_W, int l,
                                           const float* __restrict__ upd_gamma,
                                           const float* __restrict__ upd_beta) {
    __shared__ float ssc[64], ssh[64];
    if (l > 0 && threadIdx.x < 64) {
        int f = threadIdx.x;
        const double* st = d_stats + (l - 1) * 256 + 128;
        double mu  = st[f] / (double)NN;
        double var = st[64 + f] / (double)NN - mu * mu;
        float sc = upd_gamma[(l - 1) * 64 + f] * rsqrtf((float)var + 1e-5f);
        ssc[f] = sc;
        ssh[f] = upd_beta[(l - 1) * 64 + f] - (float)mu * sc;
    }
    __syncthreads();
    const float* W = msg_W + l * 96 * 64;
    const float* in = (l == 0) ? d_h : d_u;
    int lane = threadIdx.x & 31;
    int half = (threadIdx.x >> 5) & 1;
    int pib  = (threadIdx.x >> 6);       // 0..3
    float w0[32], w1[32];
    float bias0 = 0.f, bias1 = 0.f;
#pragma unroll
    for (int kk = 0; kk < 32; kk++) {
        int k = half * 32 + kk;
        float wa = W[k * 64 + lane], wb = W[k * 64 + lane + 32];
        if (l > 0) {
            bias0 = fmaf(ssh[k], wa, bias0); bias1 = fmaf(ssh[k], wb, bias1);
            float s = ssc[k]; wa *= s; wb *= s;
        }
        w0[kk] = wa; w1[kk] = wb;
    }
    __shared__ float2 red[2][4][4][32];  // [buf][pib][t][lane]
    float2* p2 = (float2*)d_p;
    int stride = gridDim.x * 16;         // 16 nodes/block/iter
    int buf = 0;
    for (int nb = blockIdx.x * 16; nb < NN; nb += stride) {
        int base = nb + pib * 4;
        float iv[4];
        bool act[4];
#pragma unroll
        for (int t = 0; t < 4; t++) {
            int n = base + t;
            act[t] = (n < NN);
            iv[t] = act[t] ? in[(size_t)n * 64 + half * 32 + lane] : 0.f;
        }
        float a0r[4], a1r[4];
#pragma unroll
        for (int t = 0; t < 4; t++) {
            float a0 = bias0, a1 = bias1;
#pragma unroll
            for (int kk = 0; kk < 32; kk++) {
                float bc = __shfl_sync(0xffffffffu, iv[t], kk);
                a0 = fmaf(bc, w0[kk], a0); a1 = fmaf(bc, w1[kk], a1);
            }
            a0r[t] = a0; a1r[t] = a1;
            if (half == 1) red[buf][pib][t][lane] = make_float2(a0, a1);
        }
        __syncthreads();
        if (half == 0) {
#pragma unroll
            for (int t = 0; t < 4; t++) {
                if (act[t]) {
                    float2 o = red[buf][pib][t][lane];
                    p2[(size_t)(base + t) * 32 + lane] =
                        make_float2(a0r[t] + o.x, a1r[t] + o.y);
                }
            }
        }
        buf ^= 1;
    }
}

// HOT (profiled): R13-exact 2-edge k_edge
__global__ __launch_bounds__(128) void k_edge(int l) {
    int lane = threadIdx.x & 31;
    const float* C = d_C + l * 1024;
    float cw0[16], cw1[16];
#pragma unroll
    for (int k = 0; k < 16; k++) { cw0[k] = C[k * 64 + lane]; cw1[k] = C[k * 64 + lane + 32]; }
    float cb0 = d_cv[l * 64 + lane], cb1 = d_cv[l * 64 + lane + 32];
    float s0 = 0.f, q0 = 0.f, s1 = 0.f, q1 = 0.f;
    const float2* p2 = (const float2*)d_p;
    int gw = (blockIdx.x * blockDim.x + threadIdx.x) >> 5;
    int nw = (gridDim.x * blockDim.x) >> 5;
    for (int n = gw; n < NN; n += nw) {
        int deg = __ldg(&d_cnt[n]);
        deg = (deg > CAP) ? CAP : deg;
        const int2* bp = d_se + (size_t)n * CAP;
        float a0 = 0.f, a1 = 0.f;
        if (deg > 0) {
            int4 cur = __ldg((const int4*)bp);
            for (int j = 0; j < deg; j += 2) {
                int4 nxt = __ldg((const int4*)(bp + j + 2));
                float2 pa = __ldg(&p2[(size_t)cur.x * 32 + lane]);
                float2 pb = __ldg(&p2[(size_t)cur.z * 32 + lane]);
                const uint4* apA = (const uint4*)(d_attrH + (size_t)cur.y * 16);
                const uint4* apB = (const uint4*)(d_attrH + (size_t)cur.w * 16);
                uint4 Aa = __ldg(apA), Ab = __ldg(apA + 1);
                uint4 Ba = __ldg(apB), Bb = __ldg(apB + 1);
                float flagB = (j + 1 < deg) ? 1.f : 0.f;
                float2 A0 = h2f(Aa.x), A1 = h2f(Aa.y), A2 = h2f(Aa.z), A3 = h2f(Aa.w);
                float2 A4 = h2f(Ab.x), A5 = h2f(Ab.y), A6 = h2f(Ab.z), A7 = h2f(Ab.w);
                float2 B0 = h2f(Ba.x), B1 = h2f(Ba.y), B2 = h2f(Ba.z), B3 = h2f(Ba.w);
                float2 B4 = h2f(Bb.x), B5 = h2f(Bb.y), B6 = h2f(Bb.z), B7 = h2f(Bb.w);
                float ma0 = pa.x + cb0, ma1 = pa.y + cb1;
                float mb0 = pb.x + cb0, mb1 = pb.y + cb1;
                ma0 = fmaf(A0.x, cw0[0], ma0);  ma1 = fmaf(A0.x, cw1[0], ma1);
                mb0 = fmaf(B0.x, cw0[0], mb0);  mb1 = fmaf(B0.x, cw1[0], mb1);
                ma0 = fmaf(A0.y, cw0[1], ma0);  ma1 = fmaf(A0.y, cw1[1], ma1);
                mb0 = fmaf(B0.y, cw0[1], mb0);  mb1 = fmaf(B0.y, cw1[1], mb1);
                ma0 = fmaf(A1.x, cw0[2], ma0);  ma1 = fmaf(A1.x, cw1[2], ma1);
                mb0 = fmaf(B1.x, cw0[2], mb0);  mb1 = fmaf(B1.x, cw1[2], mb1);
                ma0 = fmaf(A1.y, cw0[3], ma0);  ma1 = fmaf(A1.y, cw1[3], ma1);
                mb0 = fmaf(B1.y, cw0[3], mb0);  mb1 = fmaf(B1.y, cw1[3], mb1);
                ma0 = fmaf(A2.x, cw0[4], ma0);  ma1 = fmaf(A2.x, cw1[4], ma1);
                mb0 = fmaf(B2.x, cw0[4], mb0);  mb1 = fmaf(B2.x, cw1[4], mb1);
                ma0 = fmaf(A2.y, cw0[5], ma0);  ma1 = fmaf(A2.y, cw1[5], ma1);
                mb0 = fmaf(B2.y, cw0[5], mb0);  mb1 = fmaf(B2.y, cw1[5], mb1);
                ma0 = fmaf(A3.x, cw0[6], ma0);  ma1 = fmaf(A3.x, cw1[6], ma1);
                mb0 = fmaf(B3.x, cw0[6], mb0);  mb1 = fmaf(B3.x, cw1[6], mb1);
                ma0 = fmaf(A3.y, cw0[7], ma0);  ma1 = fmaf(A3.y, cw1[7], ma1);
                mb0 = fmaf(B3.y, cw0[7], mb0);  mb1 = fmaf(B3.y, cw1[7], mb1);
                ma0 = fmaf(A4.x, cw0[8], ma0);  ma1 = fmaf(A4.x, cw1[8], ma1);
                mb0 = fmaf(B4.x, cw0[8], mb0);  mb1 = fmaf(B4.x, cw1[8], mb1);
                ma0 = fmaf(A4.y, cw0[9], ma0);  ma1 = fmaf(A4.y, cw1[9], ma1);
                mb0 = fmaf(B4.y, cw0[9], mb0);  mb1 = fmaf(B4.y, cw1[9], mb1);
                ma0 = fmaf(A5.x, cw0[10], ma0); ma1 = fmaf(A5.x, cw1[10], ma1);
                mb0 = fmaf(B5.x, cw0[10], mb0); mb1 = fmaf(B5.x, cw1[10], mb1);
                ma0 = fmaf(A5.y, cw0[11], ma0); ma1 = fmaf(A5.y, cw1[11], ma1);
                mb0 = fmaf(B5.y, cw0[11], mb0); mb1 = fmaf(B5.y, cw1[11], mb1);
                ma0 = fmaf(A6.x, cw0[12], ma0); ma1 = fmaf(A6.x, cw1[12], ma1);
                mb0 = fmaf(B6.x, cw0[12], mb0); mb1 = fmaf(B6.x, cw1[12], mb1);
                ma0 = fmaf(A6.y, cw0[13], ma0); ma1 = fmaf(A6.y, cw1[13], ma1);
                mb0 = fmaf(B6.y, cw0[13], mb0); mb1 = fmaf(B6.y, cw1[13], mb1);
                ma0 = fmaf(A7.x, cw0[14], ma0); ma1 = fmaf(A7.x, cw1[14], ma1);
                mb0 = fmaf(B7.x, cw0[14], mb0); mb1 = fmaf(B7.x, cw1[14], mb1);
                ma0 = fmaf(A7.y, cw0[15], ma0); ma1 = fmaf(A7.y, cw1[15], ma1);
                mb0 = fmaf(B7.y, cw0[15], mb0); mb1 = fmaf(B7.y, cw1[15], mb1);
                ma0 = fmaxf(ma0, 0.f); ma1 = fmaxf(ma1, 0.f);
                mb0 = fmaxf(mb0, 0.f) * flagB; mb1 = fmaxf(mb1, 0.f) * flagB;
                a0 += ma0 + mb0; a1 += ma1 + mb1;
                q0 = fmaf(ma0, ma0, q0); q1 = fmaf(ma1, ma1, q1);
                q0 = fmaf(mb0, mb0, q0); q1 = fmaf(mb1, mb1, q1);
                cur = nxt;
            }
        }
        d_agg[n * 64 + lane]      = a0;
        d_agg[n * 64 + lane + 32] = a1;
        s0 += a0; s1 += a1;
    }
    __shared__ float sS[64], sQ[64];
    int t = threadIdx.x;
    if (t < 64) { sS[t] = 0.f; sQ[t] = 0.f; }
    __syncthreads();
    atomicAdd(&sS[lane], s0);      atomicAdd(&sS[lane + 32], s1);
    atomicAdd(&sQ[lane], q0);      atomicAdd(&sQ[lane + 32], q1);
    __syncthreads();
    double* st = d_stats + l * 256;
    if (t < 64) { atomicAdd(&st[t], (double)sS[t]); atomicAdd(&st[64 + t], (double)sQ[t]); }
}

// u = relu(affine(h)@Wu_h + affine(agg)@Wu_a + b); 4 nodes per warp-group per iter
__global__ __launch_bounds__(256) void k_update(const float* __restrict__ upd_W,
                                                const float* __restrict__ upd_b, int l,
                                                const float* __restrict__ msg_gamma,
                                                const float* __restrict__ msg_beta,
                                                const float* __restrict__ upd_gamma,
                                                const float* __restrict__ upd_beta) {
    __shared__ float smsc[64], smsh[64], spsc[64], spsh[64];
    if (threadIdx.x < 64) {
        int f = threadIdx.x;
        const double* st = d_stats + l * 256;
        double mu  = st[f] / (double)NE;
        double var = st[64 + f] / (double)NE - mu * mu;
        float sc = msg_gamma[l * 64 + f] * rsqrtf((float)var + 1e-5f);
        smsc[f] = sc;
        smsh[f] = msg_beta[l * 64 + f] - (float)mu * sc;
    } else if (threadIdx.x < 128 && l > 0) {
        int f = threadIdx.x - 64;
        const double* st = d_stats + (l - 1) * 256 + 128;
        double mu  = st[f] / (double)NN;
        double var = st[64 + f] / (double)NN - mu * mu;
        float sc = upd_gamma[(l - 1) * 64 + f] * rsqrtf((float)var + 1e-5f);
        spsc[f] = sc;
        spsh[f] = upd_beta[(l - 1) * 64 + f] - (float)mu * sc;
    }
    __syncthreads();
    const float* W = upd_W + l * 128 * 64;
    const float* in = (l == 0) ? d_h : d_u;
    int lane = threadIdx.x & 31;
    int sub  = (threadIdx.x >> 5) & 3;
    int slot = threadIdx.x >> 7;
    float w0[32], w1[32];
    float bias0 = 0.f, bias1 = 0.f;
#pragma unroll
    for (int kk = 0; kk < 32; kk++) {
        int k = sub * 32 + kk;
        float wa = W[k * 64 + lane], wb = W[k * 64 + lane + 32];
        if (sub < 2) {
            if (l > 0) {
                bias0 = fmaf(spsh[k], wa, bias0); bias1 = fmaf(spsh[k], wb, bias1);
                float s = spsc[k]; wa *= s; wb *= s;
            }
        } else {
            int ka = k - 64;
            bias0 = fmaf(smsh[ka], wa, bias0); bias1 = fmaf(smsh[ka], wb, bias1);  // ×deg later
            float s = smsc[ka]; wa *= s; wb *= s;
        }
        w0[kk] = wa; w1[kk] = wb;
    }
    float b0 = upd_b[l * 64 + lane], b1 = upd_b[l * 64 + lane + 32];
    __shared__ float2 red[2][2][4][4][32];   // [buf][slot][sub][t][lane]
    float s0 = 0.f, q0 = 0.f, s1 = 0.f, q1 = 0.f;
    int stride = gridDim.x * 8;              // 8 nodes/block/iter
    int buf = 0;
    for (int nb = blockIdx.x * 8; nb < NN; nb += stride) {
        int base = nb + slot * 4;
        float iv[4], degf[4];
        bool act[4];
#pragma unroll
        for (int t = 0; t < 4; t++) {
            int n = base + t;
            act[t] = (n < NN);
            if (sub < 2) {
                iv[t] = act[t] ? in[(size_t)n * 64 + sub * 32 + lane] : 0.f;
                degf[t] = 0.f;
            } else {
                iv[t] = act[t] ? d_agg[(size_t)n * 64 + (sub - 2) * 32 + lane] : 0.f;
                degf[t] = act[t] ? (float)__ldg(&d_cnt[n]) : 0.f;
            }
        }
        float a0r[4], a1r[4];
#pragma unroll
        for (int t = 0; t < 4; t++) {
            float a0, a1;
            if (sub < 2) { a0 = bias0; a1 = bias1; }
            else { a0 = degf[t] * bias0; a1 = degf[t] * bias1; }
#pragma unroll
            for (int kk = 0; kk < 32; kk++) {
                float bc = __shfl_sync(0xffffffffu, iv[t], kk);
                a0 = fmaf(bc, w0[kk], a0); a1 = fmaf(bc, w1[kk], a1);
            }
            a0r[t] = a0; a1r[t] = a1;
            if (sub) red[buf][slot][sub][t][lane] = make_float2(a0, a1);
        }
        __syncthreads();
        if (sub == 0) {
#pragma unroll
            for (int t = 0; t < 4; t++) {
                if (act[t]) {
                    float2 r1 = red[buf][slot][1][t][lane];
                    float2 r2 = red[buf][slot][2][t][lane];
                    float2 r3 = red[buf][slot][3][t][lane];
                    float v0 = a0r[t] + r1.x + r2.x + r3.x + b0;
                    float v1 = a1r[t] + r1.y + r2.y + r3.y + b1;
                    v0 = fmaxf(v0, 0.f); v1 = fmaxf(v1, 0.f);
                    int n = base + t;
                    d_u[(size_t)n * 64 + lane]      = v0;
                    d_u[(size_t)n * 64 + lane + 32] = v1;
                    s0 += v0; q0 = fmaf(v0, v0, q0);
                    s1 += v1; q1 = fmaf(v1, v1, q1);
                }
            }
        }
        buf ^= 1;
    }
    __shared__ float sS[64], sQ[64];
    int t = threadIdx.x;
    if (t < 64) { sS[t] = 0.f; sQ[t] = 0.f; }
    __syncthreads();
    if (sub == 0) {
        atomicAdd(&sS[lane], s0);      atomicAdd(&sS[lane + 32], s1);
        atomicAdd(&sQ[lane], q0);      atomicAdd(&sQ[lane + 32], q1);
    }
    __syncthreads();
    double* st = d_stats + l * 256 + 128;
    if (t < 64) { atomicAdd(&st[t], (double)sS[t]); atomicAdd(&st[64 + t], (double)sQ[t]); }
}

// segmented pool (raw u + counts); self-cleans d_cnt
#define PL_BLOCKS 128
__global__ __launch_bounds__(256) void k_pool(const int* __restrict__ batch) {
    for (int i = blockIdx.x * blockDim.x + threadIdx.x; i < NN; i += PL_BLOCKS * 256)
        d_cnt[i] = 0;
    int lane = threadIdx.x & 31;
    int w = (blockIdx.x * 256 + threadIdx.x) >> 5;
    const int chunk = (NN + 1023) / 1024;
    int s = w * chunk, e = s + chunk;
    if (e > NN) e = NN;
    if (s >= NN) return;
    int curg = __ldg(&batch[s]);
    float A0 = 0.f, A1 = 0.f; int cnt = 0;
    for (int n = s; n < e; n++) {
        int g = __ldg(&batch[n]);
        if (g != curg) {
            atomicAdd(&d_gpool[curg * 64 + lane],      A0);
            atomicAdd(&d_gpool[curg * 64 + lane + 32], A1);
            if (lane == 0) atomicAdd(&d_gcnt[curg], cnt);
            curg = g; A0 = 0.f; A1 = 0.f; cnt = 0;
        }
        A0 += d_u[n * 64 + lane];
        A1 += d_u[n * 64 + lane + 32];
        cnt++;
    }
    atomicAdd(&d_gpool[curg * 64 + lane],      A0);
    atomicAdd(&d_gpool[curg * 64 + lane + 32], A1);
    if (lane == 0) atomicAdd(&d_gcnt[curg], cnt);
}

// readout: final BN affine inline; self-cleans pool/cnt
__global__ void k_readout(const float* __restrict__ r1_W, const float* __restrict__ r1_b,
                          const float* __restrict__ r2_W, const float* __restrict__ r2_b,
                          const float* __restrict__ upd_gamma,
                          const float* __restrict__ upd_beta,
                          float* __restrict__ out) {
    int gid = blockIdx.x, f = threadIdx.x;
    __shared__ float gv[64];
    const double* st = d_stats + 2 * 256 + 128;
    double mu  = st[f] / (double)NN;
    double var = st[64 + f] / (double)NN - mu * mu;
    float sc = upd_gamma[2 * 64 + f] * rsqrtf((float)var + 1e-5f);
    float sh = upd_beta[2 * 64 + f] - (float)mu * sc;
    float cntf = (float)d_gcnt[gid];
    gv[f] = fmaf(sc, d_gpool[gid * 64 + f], cntf * sh);
    __syncthreads();
    d_gpool[gid * 64 + f] = 0.f;
    if (f == 0) d_gcnt[gid] = 0;
    float acc = r1_b[f];
    for (int k = 0; k < 64; k++)
        acc = fmaf(gv[k], r1_W[k * 64 + f], acc);
    acc = fmaxf(acc, 0.f);
    float val = acc * r2_W[f];
    __shared__ float sh2[64];
    sh2[f] = val;
    __syncthreads();
    if (f < 32) sh2[f] += sh2[f + 32];
    __syncthreads();
    if (f < 16) sh2[f] += sh2[f + 16];
    __syncthreads();
    if (f < 8) sh2[f] += sh2[f + 8];
    __syncthreads();
    if (f < 4) sh2[f] += sh2[f + 4];
    __syncthreads();
    if (f < 2) sh2[f] += sh2[f + 2];
    __syncthreads();
    if (f == 0) out[gid] = sh2[0] + sh2[1] + r2_b[0];
}

extern "C" void kernel_launch(void* const* d_in, const int* in_sizes, int n_in,
                              void* d_out, int out_size) {
    const float* x         = (const float*)d_in[0];
    const float* edge_attr = (const float*)d_in[1];
    const int*   edge_idx  = (const int*)d_in[2];
    const int*   batch     = (const int*)d_in[3];
    const float* node_W    = (const float*)d_in[4];
    const float* node_b    = (const float*)d_in[5];
    const float* edge_W    = (const float*)d_in[6];
    const float* edge_b    = (const float*)d_in[7];
    const float* msg_W     = (const float*)d_in[8];
    const float* msg_b     = (const float*)d_in[9];
    const float* msg_gamma = (const float*)d_in[10];
    const float* msg_beta  = (const float*)d_in[11];
    const float* upd_W     = (const float*)d_in[12];
    const float* upd_b     = (const float*)d_in[13];
    const float* upd_gamma = (const float*)d_in[14];
    const float* upd_beta  = (const float*)d_in[15];
    const float* r1_W      = (const float*)d_in[16];
    const float* r1_b      = (const float*)d_in[17];
    const float* r2_W      = (const float*)d_in[18];
    const float* r2_b      = (const float*)d_in[19];
    float* out = (float*)d_out;

    const int* src = edge_idx;
    const int* dst = edge_idx + NE;

    k_scatter<<<2048, 256>>>(src, dst, edge_attr);                 // 0
    k_embed<<<EM_BLOCKS + 1, 256>>>(x, node_W, node_b,
                                    edge_W, edge_b, msg_W, msg_b); // 1
    for (int l = 0; l < 3; l++) {
        k_p<<<1024, 256>>>(msg_W, l, upd_gamma, upd_beta);
        k_edge<<<4096, 128>>>(l);
        k_update<<<1024, 256>>>(upd_W, upd_b, l, msg_gamma, msg_beta,
                                upd_gamma, upd_beta);
    }
    k_pool<<<PL_BLOCKS, 256>>>(batch);
    k_readout<<<NG, 64>>>(r1_W, r1_b, r2_W, r2_b, upd_gamma, upd_beta, out);
}

// round 15
// speedup vs baseline: 1.2145x; 1.0015x over previous
#include <cuda_runtime.h>
#include <cuda_fp16.h>

#define NN 100000
#define NE 1600000
#define NG 1000
#define CAP 64

// ---------------- scratch (device globals; zero-initialized at load) ----------------
__device__ float  d_h[NN * 64];
__device__ float  d_p[NN * 64];     // float2-interleaved
__device__ float  d_u[NN * 64];
__device__ float  d_agg[NN * 64];
__device__ __half d_attrH[NE * 16];
__device__ float  d_gpool[NG * 64];
__device__ int    d_gcnt[NG];
__device__ int    d_cnt[NN];          // zero-init; re-zeroed by k_pool each run
__device__ int2   d_se[NN * CAP + 8];
__device__ float  d_C[3 * 16 * 64];
__device__ float  d_cv[3 * 64];
__device__ double d_stats[3 * 256];   // cleaned by k_scatter each run

__device__ __forceinline__ unsigned pkh2(float lo, float hi) {
    __half2 h = __floats2half2_rn(lo, hi);
    return *reinterpret_cast<unsigned*>(&h);
}
__device__ __forceinline__ float2 h2f(unsigned u) {
    return __half22float2(*reinterpret_cast<__half2*>(&u));
}

// launch 0: bucket scatter + fp16 attr conversion (fused) + stats clean
__global__ __launch_bounds__(256) void k_scatter(const int* __restrict__ src,
                                                 const int* __restrict__ dst,
                                                 const float* __restrict__ attr) {
    int tid0 = blockIdx.x * blockDim.x + threadIdx.x;
    if (tid0 < 3 * 256) d_stats[tid0] = 0.0;
    int stride = gridDim.x * blockDim.x;
    for (int i = tid0; i < NE; i += stride) {
        int d = dst[i];
        int pos = atomicAdd(&d_cnt[d], 1);
        if (pos < CAP) d_se[d * CAP + pos] = make_int2(src[i], i);
        const float4* a4 = (const float4*)(attr + (size_t)i * 16);
        float4 v0 = a4[0], v1 = a4[1], v2 = a4[2], v3 = a4[3];
        uint4 o0, o1;
        o0.x = pkh2(v0.x, v0.y); o0.y = pkh2(v0.z, v0.w);
        o0.z = pkh2(v1.x, v1.y); o0.w = pkh2(v1.z, v1.w);
        o1.x = pkh2(v2.x, v2.y); o1.y = pkh2(v2.z, v2.w);
        o1.z = pkh2(v3.x, v3.y); o1.w = pkh2(v3.z, v3.w);
        uint4* hp = (uint4*)(d_attrH + (size_t)i * 16);
        hp[0] = o0; hp[1] = o1;
    }
}

// launch 1: embed + FUSED p(l=0) (h stays warp-resident) + composite-C (last block)
#define EM_BLOCKS 512
__global__ __launch_bounds__(256) void k_embedP(const float* __restrict__ x,
                                                const float* __restrict__ node_W,
                                                const float* __restrict__ node_b,
                                                const float* __restrict__ edge_W,
                                                const float* __restrict__ edge_b,
                                                const float* __restrict__ msg_W,
                                                const float* __restrict__ msg_b) {
    int b = blockIdx.x;
    if (b < EM_BLOCKS) {
        int lane = threadIdx.x & 31;
        float w0[32], w1[32];
#pragma unroll
        for (int k = 0; k < 32; k++) { w0[k] = node_W[k * 64 + lane]; w1[k] = node_W[k * 64 + lane + 32]; }
        float b0 = node_b[lane], b1 = node_b[lane + 32];
        // msg_W[0] rows 0..63 (p projection weights)
        float mA[32], mB[32], mC[32], mD[32];
#pragma unroll
        for (int k = 0; k < 32; k++) {
            mA[k] = msg_W[k * 64 + lane];
            mB[k] = msg_W[(k + 32) * 64 + lane];
            mC[k] = msg_W[k * 64 + lane + 32];
            mD[k] = msg_W[(k + 32) * 64 + lane + 32];
        }
        float2* p2 = (float2*)d_p;
        int gw = (b * 256 + threadIdx.x) >> 5;
        int nw = (EM_BLOCKS * 256) >> 5;
        for (int n = gw; n < NN; n += nw) {
            float xv = x[n * 32 + lane];
            float a0 = b0, a1 = b1;
#pragma unroll
            for (int k = 0; k < 32; k++) {
                float bc = __shfl_sync(0xffffffffu, xv, k);
                a0 = fmaf(bc, w0[k], a0); a1 = fmaf(bc, w1[k], a1);
            }
            d_h[n * 64 + lane] = a0; d_h[n * 64 + lane + 32] = a1;
            // p(l=0) = h @ msg_W[0][0:64,:], h warp-resident as (a0, a1)
            float p0 = 0.f, p1 = 0.f;
#pragma unroll
            for (int k = 0; k < 32; k++) {
                float h0 = __shfl_sync(0xffffffffu, a0, k);
                float h1 = __shfl_sync(0xffffffffu, a1, k);
                p0 = fmaf(h0, mA[k], p0); p0 = fmaf(h1, mB[k], p0);
                p1 = fmaf(h0, mC[k], p1); p1 = fmaf(h1, mD[k], p1);
            }
            p2[(size_t)n * 32 + lane] = make_float2(p0, p1);
        }
    } else {
        int t = threadIdx.x;
        if (t < 192) {
            int l = t >> 6, f = t & 63;
            const float* Wm = msg_W + l * 96 * 64 + 64 * 64;
            for (int kk = 0; kk < 16; kk++) {
                float s = 0.f;
                for (int j = 0; j < 32; j++) s = fmaf(edge_W[kk * 32 + j], Wm[j * 64 + f], s);
                d_C[l * 1024 + kk * 64 + f] = s;
            }
            float cv = msg_b[l * 64 + f];
            for (int j = 0; j < 32; j++) cv = fmaf(edge_b[j], Wm[j * 64 + f], cv);
            d_cv[l * 64 + f] = cv;
        }
    }
}

// p = in @ msg_W[l][0:64,:] for l=1,2; 4 nodes per warp-pair per iteration
__global__ __launch_bounds__(256) void k_p(const float* __restrict__ msg_W, int l,
                                           const float* __restrict__ upd_gamma,
                                           const float* __restrict__ upd_beta) {
    __shared__ float ssc[64], ssh[64];
    if (threadIdx.x < 64) {
        int f = threadIdx.x;
        const double* st = d_stats + (l - 1) * 256 + 128;
        double mu  = st[f] / (double)NN;
        double var = st[64 + f] / (double)NN - mu * mu;
        float sc = upd_gamma[(l - 1) * 64 + f] * rsqrtf((float)var + 1e-5f);
        ssc[f] = sc;
        ssh[f] = upd_beta[(l - 1) * 64 + f] - (float)mu * sc;
    }
    __syncthreads();
    const float* W = msg_W + l * 96 * 64;
    const float* in = d_u;
    int lane = threadIdx.x & 31;
    int half = (threadIdx.x >> 5) & 1;
    int pib  = (threadIdx.x >> 6);
    float w0[32], w1[32];
    float bias0 = 0.f, bias1 = 0.f;
#pragma unroll
    for (int kk = 0; kk < 32; kk++) {
        int k = half * 32 + kk;
        float wa = W[k * 64 + lane], wb = W[k * 64 + lane + 32];
        bias0 = fmaf(ssh[k], wa, bias0); bias1 = fmaf(ssh[k], wb, bias1);
        float s = ssc[k]; wa *= s; wb *= s;
        w0[kk] = wa; w1[kk] = wb;
    }
    __shared__ float2 red[2][4][4][32];
    float2* p2 = (float2*)d_p;
    int stride = gridDim.x * 16;
    int buf = 0;
    for (int nb = blockIdx.x * 16; nb < NN; nb += stride) {
        int base = nb + pib * 4;
        float iv[4];
        bool act[4];
#pragma unroll
        for (int t = 0; t < 4; t++) {
            int n = base + t;
            act[t] = (n < NN);
            iv[t] = act[t] ? in[(size_t)n * 64 + half * 32 + lane] : 0.f;
        }
        float a0r[4], a1r[4];
#pragma unroll
        for (int t = 0; t < 4; t++) {
            float a0 = bias0, a1 = bias1;
#pragma unroll
            for (int kk = 0; kk < 32; kk++) {
                float bc = __shfl_sync(0xffffffffu, iv[t], kk);
                a0 = fmaf(bc, w0[kk], a0); a1 = fmaf(bc, w1[kk], a1);
            }
            a0r[t] = a0; a1r[t] = a1;
            if (half == 1) red[buf][pib][t][lane] = make_float2(a0, a1);
        }
        __syncthreads();
        if (half == 0) {
#pragma unroll
            for (int t = 0; t < 4; t++) {
                if (act[t]) {
                    float2 o = red[buf][pib][t][lane];
                    p2[(size_t)(base + t) * 32 + lane] =
                        make_float2(a0r[t] + o.x, a1r[t] + o.y);
                }
            }
        }
        buf ^= 1;
    }
}

// HOT: R13-exact 2-edge k_edge
__global__ __launch_bounds__(128) void k_edge(int l) {
    int lane = threadIdx.x & 31;
    const float* C = d_C + l * 1024;
    float cw0[16], cw1[16];
#pragma unroll
    for (int k = 0; k < 16; k++) { cw0[k] = C[k * 64 + lane]; cw1[k] = C[k * 64 + lane + 32]; }
    float cb0 = d_cv[l * 64 + lane], cb1 = d_cv[l * 64 + lane + 32];
    float s0 = 0.f, q0 = 0.f, s1 = 0.f, q1 = 0.f;
    const float2* p2 = (const float2*)d_p;
    int gw = (blockIdx.x * blockDim.x + threadIdx.x) >> 5;
    int nw = (gridDim.x * blockDim.x) >> 5;
    for (int n = gw; n < NN; n += nw) {
        int deg = __ldg(&d_cnt[n]);
        deg = (deg > CAP) ? CAP : deg;
        const int2* bp = d_se + (size_t)n * CAP;
        float a0 = 0.f, a1 = 0.f;
        if (deg > 0) {
            int4 cur = __ldg((const int4*)bp);
            for (int j = 0; j < deg; j += 2) {
                int4 nxt = __ldg((const int4*)(bp + j + 2));
                float2 pa = __ldg(&p2[(size_t)cur.x * 32 + lane]);
                float2 pb = __ldg(&p2[(size_t)cur.z * 32 + lane]);
                const uint4* apA = (const uint4*)(d_attrH + (size_t)cur.y * 16);
                const uint4* apB = (const uint4*)(d_attrH + (size_t)cur.w * 16);
                uint4 Aa = __ldg(apA), Ab = __ldg(apA + 1);
                uint4 Ba = __ldg(apB), Bb = __ldg(apB + 1);
                float flagB = (j + 1 < deg) ? 1.f : 0.f;
                float2 A0 = h2f(Aa.x), A1 = h2f(Aa.y), A2 = h2f(Aa.z), A3 = h2f(Aa.w);
                float2 A4 = h2f(Ab.x), A5 = h2f(Ab.y), A6 = h2f(Ab.z), A7 = h2f(Ab.w);
                float2 B0 = h2f(Ba.x), B1 = h2f(Ba.y), B2 = h2f(Ba.z), B3 = h2f(Ba.w);
                float2 B4 = h2f(Bb.x), B5 = h2f(Bb.y), B6 = h2f(Bb.z), B7 = h2f(Bb.w);
                float ma0 = pa.x + cb0, ma1 = pa.y + cb1;
                float mb0 = pb.x + cb0, mb1 = pb.y + cb1;
                ma0 = fmaf(A0.x, cw0[0], ma0);  ma1 = fmaf(A0.x, cw1[0], ma1);
                mb0 = fmaf(B0.x, cw0[0], mb0);  mb1 = fmaf(B0.x, cw1[0], mb1);
                ma0 = fmaf(A0.y, cw0[1], ma0);  ma1 = fmaf(A0.y, cw1[1], ma1);
                mb0 = fmaf(B0.y, cw0[1], mb0);  mb1 = fmaf(B0.y, cw1[1], mb1);
                ma0 = fmaf(A1.x, cw0[2], ma0);  ma1 = fmaf(A1.x, cw1[2], ma1);
                mb0 = fmaf(B1.x, cw0[2], mb0);  mb1 = fmaf(B1.x, cw1[2], mb1);
                ma0 = fmaf(A1.y, cw0[3], ma0);  ma1 = fmaf(A1.y, cw1[3], ma1);
                mb0 = fmaf(B1.y, cw0[3], mb0);  mb1 = fmaf(B1.y, cw1[3], mb1);
                ma0 = fmaf(A2.x, cw0[4], ma0);  ma1 = fmaf(A2.x, cw1[4], ma1);
                mb0 = fmaf(B2.x, cw0[4], mb0);  mb1 = fmaf(B2.x, cw1[4], mb1);
                ma0 = fmaf(A2.y, cw0[5], ma0);  ma1 = fmaf(A2.y, cw1[5], ma1);
                mb0 = fmaf(B2.y, cw0[5], mb0);  mb1 = fmaf(B2.y, cw1[5], mb1);
                ma0 = fmaf(A3.x, cw0[6], ma0);  ma1 = fmaf(A3.x, cw1[6], ma1);
                mb0 = fmaf(B3.x, cw0[6], mb0);  mb1 = fmaf(B3.x, cw1[6], mb1);
                ma0 = fmaf(A3.y, cw0[7], ma0);  ma1 = fmaf(A3.y, cw1[7], ma1);
                mb0 = fmaf(B3.y, cw0[7], mb0);  mb1 = fmaf(B3.y, cw1[7], mb1);
                ma0 = fmaf(A4.x, cw0[8], ma0);  ma1 = fmaf(A4.x, cw1[8], ma1);
                mb0 = fmaf(B4.x, cw0[8], mb0);  mb1 = fmaf(B4.x, cw1[8], mb1);
                ma0 = fmaf(A4.y, cw0[9], ma0);  ma1 = fmaf(A4.y, cw1[9], ma1);
                mb0 = fmaf(B4.y, cw0[9], mb0);  mb1 = fmaf(B4.y, cw1[9], mb1);
                ma0 = fmaf(A5.x, cw0[10], ma0); ma1 = fmaf(A5.x, cw1[10], ma1);
                mb0 = fmaf(B5.x, cw0[10], mb0); mb1 = fmaf(B5.x, cw1[10], mb1);
                ma0 = fmaf(A5.y, cw0[11], ma0); ma1 = fmaf(A5.y, cw1[11], ma1);
                mb0 = fmaf(B5.y, cw0[11], mb0); mb1 = fmaf(B5.y, cw1[11], mb1);
                ma0 = fmaf(A6.x, cw0[12], ma0); ma1 = fmaf(A6.x, cw1[12], ma1);
                mb0 = fmaf(B6.x, cw0[12], mb0); mb1 = fmaf(B6.x, cw1[12], mb1);
                ma0 = fmaf(A6.y, cw0[13], ma0); ma1 = fmaf(A6.y, cw1[13], ma1);
                mb0 = fmaf(B6.y, cw0[13], mb0); mb1 = fmaf(B6.y, cw1[13], mb1);
                ma0 = fmaf(A7.x, cw0[14], ma0); ma1 = fmaf(A7.x, cw1[14], ma1);
                mb0 = fmaf(B7.x, cw0[14], mb0); mb1 = fmaf(B7.x, cw1[14], mb1);
                ma0 = fmaf(A7.y, cw0[15], ma0); ma1 = fmaf(A7.y, cw1[15], ma1);
                mb0 = fmaf(B7.y, cw0[15], mb0); mb1 = fmaf(B7.y, cw1[15], mb1);
                ma0 = fmaxf(ma0, 0.f); ma1 = fmaxf(ma1, 0.f);
                mb0 = fmaxf(mb0, 0.f) * flagB; mb1 = fmaxf(mb1, 0.f) * flagB;
                a0 += ma0 + mb0; a1 += ma1 + mb1;
                q0 = fmaf(ma0, ma0, q0); q1 = fmaf(ma1, ma1, q1);
                q0 = fmaf(mb0, mb0, q0); q1 = fmaf(mb1, mb1, q1);
                cur = nxt;
            }
        }
        d_agg[n * 64 + lane]      = a0;
        d_agg[n * 64 + lane + 32] = a1;
        s0 += a0; s1 += a1;
    }
    __shared__ float sS[64], sQ[64];
    int t = threadIdx.x;
    if (t < 64) { sS[t] = 0.f; sQ[t] = 0.f; }
    __syncthreads();
    atomicAdd(&sS[lane], s0);      atomicAdd(&sS[lane + 32], s1);
    atomicAdd(&sQ[lane], q0);      atomicAdd(&sQ[lane + 32], q1);
    __syncthreads();
    double* st = d_stats + l * 256;
    if (t < 64) { atomicAdd(&st[t], (double)sS[t]); atomicAdd(&st[64 + t], (double)sQ[t]); }
}

// u = relu(affine(h)@Wu_h + affine(agg)@Wu_a + b); 4 nodes per warp-group per iter
__global__ __launch_bounds__(256) void k_update(const float* __restrict__ upd_W,
                                                const float* __restrict__ upd_b, int l,
                                                const float* __restrict__ msg_gamma,
                                                const float* __restrict__ msg_beta,
                                                const float* __restrict__ upd_gamma,
                                                const float* __restrict__ upd_beta) {
    __shared__ float smsc[64], smsh[64], spsc[64], spsh[64];
    if (threadIdx.x < 64) {
        int f = threadIdx.x;
        const double* st = d_stats + l * 256;
        double mu  = st[f] / (double)NE;
        double var = st[64 + f] / (double)NE - mu * mu;
        float sc = msg_gamma[l * 64 + f] * rsqrtf((float)var + 1e-5f);
        smsc[f] = sc;
        smsh[f] = msg_beta[l * 64 + f] - (float)mu * sc;
    } else if (threadIdx.x < 128 && l > 0) {
        int f = threadIdx.x - 64;
        const double* st = d_stats + (l - 1) * 256 + 128;
        double mu  = st[f] / (double)NN;
        double var = st[64 + f] / (double)NN - mu * mu;
        float sc = upd_gamma[(l - 1) * 64 + f] * rsqrtf((float)var + 1e-5f);
        spsc[f] = sc;
        spsh[f] = upd_beta[(l - 1) * 64 + f] - (float)mu * sc;
    }
    __syncthreads();
    const float* W = upd_W + l * 128 * 64;
    const float* in = (l == 0) ? d_h : d_u;
    int lane = threadIdx.x & 31;
    int sub  = (threadIdx.x >> 5) & 3;
    int slot = threadIdx.x >> 7;
    float w0[32], w1[32];
    float bias0 = 0.f, bias1 = 0.f;
#pragma unroll
    for (int kk = 0; kk < 32; kk++) {
        int k = sub * 32 + kk;
        float wa = W[k * 64 + lane], wb = W[k * 64 + lane + 32];
        if (sub < 2) {
            if (l > 0) {
                bias0 = fmaf(spsh[k], wa, bias0); bias1 = fmaf(spsh[k], wb, bias1);
                float s = spsc[k]; wa *= s; wb *= s;
            }
        } else {
            int ka = k - 64;
            bias0 = fmaf(smsh[ka], wa, bias0); bias1 = fmaf(smsh[ka], wb, bias1);
            float s = smsc[ka]; wa *= s; wb *= s;
        }
        w0[kk] = wa; w1[kk] = wb;
    }
    float b0 = upd_b[l * 64 + lane], b1 = upd_b[l * 64 + lane + 32];
    __shared__ float2 red[2][2][4][4][32];
    float s0 = 0.f, q0 = 0.f, s1 = 0.f, q1 = 0.f;
    int stride = gridDim.x * 8;
    int buf = 0;
    for (int nb = blockIdx.x * 8; nb < NN; nb += stride) {
        int base = nb + slot * 4;
        float iv[4], degf[4];
        bool act[4];
#pragma unroll
        for (int t = 0; t < 4; t++) {
            int n = base + t;
            act[t] = (n < NN);
            if (sub < 2) {
                iv[t] = act[t] ? in[(size_t)n * 64 + sub * 32 + lane] : 0.f;
                degf[t] = 0.f;
            } else {
                iv[t] = act[t] ? d_agg[(size_t)n * 64 + (sub - 2) * 32 + lane] : 0.f;
                degf[t] = act[t] ? (float)__ldg(&d_cnt[n]) : 0.f;
            }
        }
        float a0r[4], a1r[4];
#pragma unroll
        for (int t = 0; t < 4; t++) {
            float a0, a1;
            if (sub < 2) { a0 = bias0; a1 = bias1; }
            else { a0 = degf[t] * bias0; a1 = degf[t] * bias1; }
#pragma unroll
            for (int kk = 0; kk < 32; kk++) {
                float bc = __shfl_sync(0xffffffffu, iv[t], kk);
                a0 = fmaf(bc, w0[kk], a0); a1 = fmaf(bc, w1[kk], a1);
            }
            a0r[t] = a0; a1r[t] = a1;
            if (sub) red[buf][slot][sub][t][lane] = make_float2(a0, a1);
        }
        __syncthreads();
        if (sub == 0) {
#pragma unroll
            for (int t = 0; t < 4; t++) {
                if (act[t]) {
                    float2 r1 = red[buf][slot][1][t][lane];
                    float2 r2 = red[buf][slot][2][t][lane];
                    float2 r3 = red[buf][slot][3][t][lane];
                    float v0 = a0r[t] + r1.x + r2.x + r3.x + b0;
                    float v1 = a1r[t] + r1.y + r2.y + r3.y + b1;
                    v0 = fmaxf(v0, 0.f); v1 = fmaxf(v1, 0.f);
                    int n = base + t;
                    d_u[(size_t)n * 64 + lane]      = v0;
                    d_u[(size_t)n * 64 + lane + 32] = v1;
                    s0 += v0; q0 = fmaf(v0, v0, q0);
                    s1 += v1; q1 = fmaf(v1, v1, q1);
                }
            }
        }
        buf ^= 1;
    }
    __shared__ float sS[64], sQ[64];
    int t = threadIdx.x;
    if (t < 64) { sS[t] = 0.f; sQ[t] = 0.f; }
    __syncthreads();
    if (sub == 0) {
        atomicAdd(&sS[lane], s0);      atomicAdd(&sS[lane + 32], s1);
        atomicAdd(&sQ[lane], q0);      atomicAdd(&sQ[lane + 32], q1);
    }
    __syncthreads();
    double* st = d_stats + l * 256 + 128;
    if (t < 64) { atomicAdd(&st[t], (double)sS[t]); atomicAdd(&st[64 + t], (double)sQ[t]); }
}

// segmented pool (raw u + counts); self-cleans d_cnt
#define PL_BLOCKS 128
__global__ __launch_bounds__(256) void k_pool(const int* __restrict__ batch) {
    for (int i = blockIdx.x * blockDim.x + threadIdx.x; i < NN; i += PL_BLOCKS * 256)
        d_cnt[i] = 0;
    int lane = threadIdx.x & 31;
    int w = (blockIdx.x * 256 + threadIdx.x) >> 5;
    const int chunk = (NN + 1023) / 1024;
    int s = w * chunk, e = s + chunk;
    if (e > NN) e = NN;
    if (s >= NN) return;
    int curg = __ldg(&batch[s]);
    float A0 = 0.f, A1 = 0.f; int cnt = 0;
    for (int n = s; n < e; n++) {
        int g = __ldg(&batch[n]);
        if (g != curg) {
            atomicAdd(&d_gpool[curg * 64 + lane],      A0);
            atomicAdd(&d_gpool[curg * 64 + lane + 32], A1);
            if (lane == 0) atomicAdd(&d_gcnt[curg], cnt);
            curg = g; A0 = 0.f; A1 = 0.f; cnt = 0;
        }
        A0 += d_u[n * 64 + lane];
        A1 += d_u[n * 64 + lane + 32];
        cnt++;
    }
    atomicAdd(&d_gpool[curg * 64 + lane],      A0);
    atomicAdd(&d_gpool[curg * 64 + lane + 32], A1);
    if (lane == 0) atomicAdd(&d_gcnt[curg], cnt);
}

// readout: final BN affine inline; self-cleans pool/cnt
__global__ void k_readout(const float* __restrict__ r1_W, const float* __restrict__ r1_b,
                          const float* __restrict__ r2_W, const float* __restrict__ r2_b,
                          const float* __restrict__ upd_gamma,
                          const float* __restrict__ upd_beta,
                          float* __restrict__ out) {
    int gid = blockIdx.x, f = threadIdx.x;
    __shared__ float gv[64];
    const double* st = d_stats + 2 * 256 + 128;
    double mu  = st[f] / (double)NN;
    double var = st[64 + f] / (double)NN - mu * mu;
    float sc = upd_gamma[2 * 64 + f] * rsqrtf((float)var + 1e-5f);
    float sh = upd_beta[2 * 64 + f] - (float)mu * sc;
    float cntf = (float)d_gcnt[gid];
    gv[f] = fmaf(sc, d_gpool[gid * 64 + f], cntf * sh);
    __syncthreads();
    d_gpool[gid * 64 + f] = 0.f;
    if (f == 0) d_gcnt[gid] = 0;
    float acc = r1_b[f];
    for (int k = 0; k < 64; k++)
        acc = fmaf(gv[k], r1_W[k * 64 + f], acc);
    acc = fmaxf(acc, 0.f);
    float val = acc * r2_W[f];
    __shared__ float sh2[64];
    sh2[f] = val;
    __syncthreads();
    if (f < 32) sh2[f] += sh2[f + 32];
    __syncthreads();
    if (f < 16) sh2[f] += sh2[f + 16];
    __syncthreads();
    if (f < 8) sh2[f] += sh2[f + 8];
    __syncthreads();
    if (f < 4) sh2[f] += sh2[f + 4];
    __syncthreads();
    if (f < 2) sh2[f] += sh2[f + 2];
    __syncthreads();
    if (f == 0) out[gid] = sh2[0] + sh2[1] + r2_b[0];
}

extern "C" void kernel_launch(void* const* d_in, const int* in_sizes, int n_in,
                              void* d_out, int out_size) {
    const float* x         = (const float*)d_in[0];
    const float* edge_attr = (const float*)d_in[1];
    const int*   edge_idx  = (const int*)d_in[2];
    const int*   batch     = (const int*)d_in[3];
    const float* node_W    = (const float*)d_in[4];
    const float* node_b    = (const float*)d_in[5];
    const float* edge_W    = (const float*)d_in[6];
    const float* edge_b    = (const float*)d_in[7];
    const float* msg_W     = (const float*)d_in[8];
    const float* msg_b     = (const float*)d_in[9];
    const float* msg_gamma = (const float*)d_in[10];
    const float* msg_beta  = (const float*)d_in[11];
    const float* upd_W     = (const float*)d_in[12];
    const float* upd_b     = (const float*)d_in[13];
    const float* upd_gamma = (const float*)d_in[14];
    const float* upd_beta  = (const float*)d_in[15];
    const float* r1_W      = (const float*)d_in[16];
    const float* r1_b      = (const float*)d_in[17];
    const float* r2_W      = (const float*)d_in[18];
    const float* r2_b      = (const float*)d_in[19];
    float* out = (float*)d_out;

    const int* src = edge_idx;
    const int* dst = edge_idx + NE;

    k_scatter<<<2048, 256>>>(src, dst, edge_attr);                 // 0
    k_embedP<<<EM_BLOCKS + 1, 256>>>(x, node_W, node_b,
                                     edge_W, edge_b, msg_W, msg_b);// 1 (embed + p l=0)
    k_edge<<<4096, 128>>>(0);                                      // 2
    k_update<<<1024, 256>>>(upd_W, upd_b, 0, msg_gamma, msg_beta,
                            upd_gamma, upd_beta);                  // 3 <- profiled
    for (int l = 1; l < 3; l++) {
        k_p<<<1024, 256>>>(msg_W, l, upd_gamma, upd_beta);
        k_edge<<<4096, 128>>>(l);
        k_update<<<1024, 256>>>(upd_W, upd_b, l, msg_gamma, msg_beta,
                                upd_gamma, upd_beta);
    }
    k_pool<<<PL_BLOCKS, 256>>>(batch);
    k_readout<<<NG, 64>>>(r1_W, r1_b, r2_W, r2_b, upd_gamma, upd_beta, out);
}

// round 16
// speedup vs baseline: 1.4249x; 1.1733x over previous
#include <cuda_runtime.h>
#include <cuda_fp16.h>

#define NN 100000
#define NE 1600000
#define NG 1000
#define CAP 64

// ---------------- scratch (device globals; zero-initialized at load) ----------------
__device__ float  d_h[NN * 64];
__device__ float  d_p[NN * 64];     // float2-interleaved
__device__ float  d_u[NN * 64];
__device__ float  d_agg[NN * 64];
__device__ __half d_attrH[NE * 16];
__device__ float  d_gpool[NG * 64];
__device__ int    d_gcnt[NG];
__device__ int    d_cnt[NN];          // zero-init; re-zeroed by k_pool each run
__device__ int2   d_se[NN * CAP + 8];
__device__ float  d_C[3 * 16 * 64];
__device__ float  d_cv[3 * 64];
__device__ double d_stats[3 * 256];   // cleaned by k_scatter each run

__device__ __forceinline__ unsigned pkh2(float lo, float hi) {
    __half2 h = __floats2half2_rn(lo, hi);
    return *reinterpret_cast<unsigned*>(&h);
}
__device__ __forceinline__ float2 h2f(unsigned u) {
    return __half22float2(*reinterpret_cast<__half2*>(&u));
}

// launch 0: bucket scatter + fp16 attr conversion (fused) + stats clean
__global__ __launch_bounds__(256) void k_scatter(const int* __restrict__ src,
                                                 const int* __restrict__ dst,
                                                 const float* __restrict__ attr) {
    int tid0 = blockIdx.x * blockDim.x + threadIdx.x;
    if (tid0 < 3 * 256) d_stats[tid0] = 0.0;
    int stride = gridDim.x * blockDim.x;
    for (int i = tid0; i < NE; i += stride) {
        int d = dst[i];
        int pos = atomicAdd(&d_cnt[d], 1);
        if (pos < CAP) d_se[d * CAP + pos] = make_int2(src[i], i);
        const float4* a4 = (const float4*)(attr + (size_t)i * 16);
        float4 v0 = a4[0], v1 = a4[1], v2 = a4[2], v3 = a4[3];
        uint4 o0, o1;
        o0.x = pkh2(v0.x, v0.y); o0.y = pkh2(v0.z, v0.w);
        o0.z = pkh2(v1.x, v1.y); o0.w = pkh2(v1.z, v1.w);
        o1.x = pkh2(v2.x, v2.y); o1.y = pkh2(v2.z, v2.w);
        o1.z = pkh2(v3.x, v3.y); o1.w = pkh2(v3.z, v3.w);
        uint4* hp = (uint4*)(d_attrH + (size_t)i * 16);
        hp[0] = o0; hp[1] = o1;
    }
}

// launch 1: embed + FUSED p(l=0) + composite-C (last block)
#define EM_BLOCKS 512
__global__ __launch_bounds__(256) void k_embedP(const float* __restrict__ x,
                                                const float* __restrict__ node_W,
                                                const float* __restrict__ node_b,
                                                const float* __restrict__ edge_W,
                                                const float* __restrict__ edge_b,
                                                const float* __restrict__ msg_W,
                                                const float* __restrict__ msg_b) {
    int b = blockIdx.x;
    if (b < EM_BLOCKS) {
        int lane = threadIdx.x & 31;
        float w0[32], w1[32];
#pragma unroll
        for (int k = 0; k < 32; k++) { w0[k] = node_W[k * 64 + lane]; w1[k] = node_W[k * 64 + lane + 32]; }
        float b0 = node_b[lane], b1 = node_b[lane + 32];
        float mA[32], mB[32], mC[32], mD[32];
#pragma unroll
        for (int k = 0; k < 32; k++) {
            mA[k] = msg_W[k * 64 + lane];
            mB[k] = msg_W[(k + 32) * 64 + lane];
            mC[k] = msg_W[k * 64 + lane + 32];
            mD[k] = msg_W[(k + 32) * 64 + lane + 32];
        }
        float2* p2 = (float2*)d_p;
        int gw = (b * 256 + threadIdx.x) >> 5;
        int nw = (EM_BLOCKS * 256) >> 5;
        for (int n = gw; n < NN; n += nw) {
            float xv = x[n * 32 + lane];
            float a0 = b0, a1 = b1;
#pragma unroll
            for (int k = 0; k < 32; k++) {
                float bc = __shfl_sync(0xffffffffu, xv, k);
                a0 = fmaf(bc, w0[k], a0); a1 = fmaf(bc, w1[k], a1);
            }
            d_h[n * 64 + lane] = a0; d_h[n * 64 + lane + 32] = a1;
            float p0 = 0.f, p1 = 0.f;
#pragma unroll
            for (int k = 0; k < 32; k++) {
                float h0 = __shfl_sync(0xffffffffu, a0, k);
                float h1 = __shfl_sync(0xffffffffu, a1, k);
                p0 = fmaf(h0, mA[k], p0); p0 = fmaf(h1, mB[k], p0);
                p1 = fmaf(h0, mC[k], p1); p1 = fmaf(h1, mD[k], p1);
            }
            p2[(size_t)n * 32 + lane] = make_float2(p0, p1);
        }
    } else {
        int t = threadIdx.x;
        if (t < 192) {
            int l = t >> 6, f = t & 63;
            const float* Wm = msg_W + l * 96 * 64 + 64 * 64;
            for (int kk = 0; kk < 16; kk++) {
                float s = 0.f;
                for (int j = 0; j < 32; j++) s = fmaf(edge_W[kk * 32 + j], Wm[j * 64 + f], s);
                d_C[l * 1024 + kk * 64 + f] = s;
            }
            float cv = msg_b[l * 64 + f];
            for (int j = 0; j < 32; j++) cv = fmaf(edge_b[j], Wm[j * 64 + f], cv);
            d_cv[l * 64 + f] = cv;
        }
    }
}

// p = affine(u) @ msg_W[l][0:64,:] for l=1,2 — smem weights, warp-per-4-nodes, no barriers
__global__ __launch_bounds__(256) void k_p(const float* __restrict__ msg_W, int l,
                                           const float* __restrict__ upd_gamma,
                                           const float* __restrict__ upd_beta) {
    __shared__ float ssc[64], ssh[64];
    __shared__ float ws[64 * 64];
    __shared__ float sbias[64];
    if (threadIdx.x < 64) {
        int f = threadIdx.x;
        const double* st = d_stats + (l - 1) * 256 + 128;
        double mu  = st[f] / (double)NN;
        double var = st[64 + f] / (double)NN - mu * mu;
        float sc = upd_gamma[(l - 1) * 64 + f] * rsqrtf((float)var + 1e-5f);
        ssc[f] = sc;
        ssh[f] = upd_beta[(l - 1) * 64 + f] - (float)mu * sc;
    }
    __syncthreads();
    const float* W = msg_W + l * 96 * 64;
    for (int i = threadIdx.x; i < 4096; i += 256)
        ws[i] = W[i] * ssc[i >> 6];
    if (threadIdx.x < 64) {
        int f = threadIdx.x;
        float bsum = 0.f;
        for (int k = 0; k < 64; k++) bsum = fmaf(ssh[k], W[k * 64 + f], bsum);
        sbias[f] = bsum;
    }
    __syncthreads();
    int lane = threadIdx.x & 31;
    float bias0 = sbias[lane], bias1 = sbias[lane + 32];
    const float* in = d_u;
    float2* p2 = (float2*)d_p;
    int gw = (blockIdx.x * 256 + threadIdx.x) >> 5;
    int nw = (gridDim.x * 256) >> 5;
    for (int g = gw * 4; g < NN; g += nw * 4) {
        float iv0[4], iv1[4];
        bool act[4];
#pragma unroll
        for (int t = 0; t < 4; t++) {
            int n = g + t;
            act[t] = (n < NN);
            iv0[t] = act[t] ? in[(size_t)n * 64 + lane] : 0.f;
            iv1[t] = act[t] ? in[(size_t)n * 64 + lane + 32] : 0.f;
        }
        float a0[4] = {bias0, bias0, bias0, bias0};
        float a1[4] = {bias1, bias1, bias1, bias1};
#pragma unroll 16
        for (int k = 0; k < 32; k++) {
            float w0 = ws[k * 64 + lane], w1 = ws[k * 64 + lane + 32];
#pragma unroll
            for (int t = 0; t < 4; t++) {
                float bc = __shfl_sync(0xffffffffu, iv0[t], k);
                a0[t] = fmaf(bc, w0, a0[t]); a1[t] = fmaf(bc, w1, a1[t]);
            }
        }
#pragma unroll 16
        for (int k = 0; k < 32; k++) {
            float w0 = ws[(k + 32) * 64 + lane], w1 = ws[(k + 32) * 64 + lane + 32];
#pragma unroll
            for (int t = 0; t < 4; t++) {
                float bc = __shfl_sync(0xffffffffu, iv1[t], k);
                a0[t] = fmaf(bc, w0, a0[t]); a1[t] = fmaf(bc, w1, a1[t]);
            }
        }
#pragma unroll
        for (int t = 0; t < 4; t++)
            if (act[t])
                p2[(size_t)(g + t) * 32 + lane] = make_float2(a0[t], a1[t]);
    }
}

// HOT: R13-exact 2-edge k_edge
__global__ __launch_bounds__(128) void k_edge(int l) {
    int lane = threadIdx.x & 31;
    const float* C = d_C + l * 1024;
    float cw0[16], cw1[16];
#pragma unroll
    for (int k = 0; k < 16; k++) { cw0[k] = C[k * 64 + lane]; cw1[k] = C[k * 64 + lane + 32]; }
    float cb0 = d_cv[l * 64 + lane], cb1 = d_cv[l * 64 + lane + 32];
    float s0 = 0.f, q0 = 0.f, s1 = 0.f, q1 = 0.f;
    const float2* p2 = (const float2*)d_p;
    int gw = (blockIdx.x * blockDim.x + threadIdx.x) >> 5;
    int nw = (gridDim.x * blockDim.x) >> 5;
    for (int n = gw; n < NN; n += nw) {
        int deg = __ldg(&d_cnt[n]);
        deg = (deg > CAP) ? CAP : deg;
        const int2* bp = d_se + (size_t)n * CAP;
        float a0 = 0.f, a1 = 0.f;
        if (deg > 0) {
            int4 cur = __ldg((const int4*)bp);
            for (int j = 0; j < deg; j += 2) {
                int4 nxt = __ldg((const int4*)(bp + j + 2));
                float2 pa = __ldg(&p2[(size_t)cur.x * 32 + lane]);
                float2 pb = __ldg(&p2[(size_t)cur.z * 32 + lane]);
                const uint4* apA = (const uint4*)(d_attrH + (size_t)cur.y * 16);
                const uint4* apB = (const uint4*)(d_attrH + (size_t)cur.w * 16);
                uint4 Aa = __ldg(apA), Ab = __ldg(apA + 1);
                uint4 Ba = __ldg(apB), Bb = __ldg(apB + 1);
                float flagB = (j + 1 < deg) ? 1.f : 0.f;
                float2 A0 = h2f(Aa.x), A1 = h2f(Aa.y), A2 = h2f(Aa.z), A3 = h2f(Aa.w);
                float2 A4 = h2f(Ab.x), A5 = h2f(Ab.y), A6 = h2f(Ab.z), A7 = h2f(Ab.w);
                float2 B0 = h2f(Ba.x), B1 = h2f(Ba.y), B2 = h2f(Ba.z), B3 = h2f(Ba.w);
                float2 B4 = h2f(Bb.x), B5 = h2f(Bb.y), B6 = h2f(Bb.z), B7 = h2f(Bb.w);
                float ma0 = pa.x + cb0, ma1 = pa.y + cb1;
                float mb0 = pb.x + cb0, mb1 = pb.y + cb1;
                ma0 = fmaf(A0.x, cw0[0], ma0);  ma1 = fmaf(A0.x, cw1[0], ma1);
                mb0 = fmaf(B0.x, cw0[0], mb0);  mb1 = fmaf(B0.x, cw1[0], mb1);
                ma0 = fmaf(A0.y, cw0[1], ma0);  ma1 = fmaf(A0.y, cw1[1], ma1);
                mb0 = fmaf(B0.y, cw0[1], mb0);  mb1 = fmaf(B0.y, cw1[1], mb1);
                ma0 = fmaf(A1.x, cw0[2], ma0);  ma1 = fmaf(A1.x, cw1[2], ma1);
                mb0 = fmaf(B1.x, cw0[2], mb0);  mb1 = fmaf(B1.x, cw1[2], mb1);
                ma0 = fmaf(A1.y, cw0[3], ma0);  ma1 = fmaf(A1.y, cw1[3], ma1);
                mb0 = fmaf(B1.y, cw0[3], mb0);  mb1 = fmaf(B1.y, cw1[3], mb1);
                ma0 = fmaf(A2.x, cw0[4], ma0);  ma1 = fmaf(A2.x, cw1[4], ma1);
                mb0 = fmaf(B2.x, cw0[4], mb0);  mb1 = fmaf(B2.x, cw1[4], mb1);
                ma0 = fmaf(A2.y, cw0[5], ma0);  ma1 = fmaf(A2.y, cw1[5], ma1);
                mb0 = fmaf(B2.y, cw0[5], mb0);  mb1 = fmaf(B2.y, cw1[5], mb1);
                ma0 = fmaf(A3.x, cw0[6], ma0);  ma1 = fmaf(A3.x, cw1[6], ma1);
                mb0 = fmaf(B3.x, cw0[6], mb0);  mb1 = fmaf(B3.x, cw1[6], mb1);
                ma0 = fmaf(A3.y, cw0[7], ma0);  ma1 = fmaf(A3.y, cw1[7], ma1);
                mb0 = fmaf(B3.y, cw0[7], mb0);  mb1 = fmaf(B3.y, cw1[7], mb1);
                ma0 = fmaf(A4.x, cw0[8], ma0);  ma1 = fmaf(A4.x, cw1[8], ma1);
                mb0 = fmaf(B4.x, cw0[8], mb0);  mb1 = fmaf(B4.x, cw1[8], mb1);
                ma0 = fmaf(A4.y, cw0[9], ma0);  ma1 = fmaf(A4.y, cw1[9], ma1);
                mb0 = fmaf(B4.y, cw0[9], mb0);  mb1 = fmaf(B4.y, cw1[9], mb1);
                ma0 = fmaf(A5.x, cw0[10], ma0); ma1 = fmaf(A5.x, cw1[10], ma1);
                mb0 = fmaf(B5.x, cw0[10], mb0); mb1 = fmaf(B5.x, cw1[10], mb1);
                ma0 = fmaf(A5.y, cw0[11], ma0); ma1 = fmaf(A5.y, cw1[11], ma1);
                mb0 = fmaf(B5.y, cw0[11], mb0); mb1 = fmaf(B5.y, cw1[11], mb1);
                ma0 = fmaf(A6.x, cw0[12], ma0); ma1 = fmaf(A6.x, cw1[12], ma1);
                mb0 = fmaf(B6.x, cw0[12], mb0); mb1 = fmaf(B6.x, cw1[12], mb1);
                ma0 = fmaf(A6.y, cw0[13], ma0); ma1 = fmaf(A6.y, cw1[13], ma1);
                mb0 = fmaf(B6.y, cw0[13], mb0); mb1 = fmaf(B6.y, cw1[13], mb1);
                ma0 = fmaf(A7.x, cw0[14], ma0); ma1 = fmaf(A7.x, cw1[14], ma1);
                mb0 = fmaf(B7.x, cw0[14], mb0); mb1 = fmaf(B7.x, cw1[14], mb1);
                ma0 = fmaf(A7.y, cw0[15], ma0); ma1 = fmaf(A7.y, cw1[15], ma1);
                mb0 = fmaf(B7.y, cw0[15], mb0); mb1 = fmaf(B7.y, cw1[15], mb1);
                ma0 = fmaxf(ma0, 0.f); ma1 = fmaxf(ma1, 0.f);
                mb0 = fmaxf(mb0, 0.f) * flagB; mb1 = fmaxf(mb1, 0.f) * flagB;
                a0 += ma0 + mb0; a1 += ma1 + mb1;
                q0 = fmaf(ma0, ma0, q0); q1 = fmaf(ma1, ma1, q1);
                q0 = fmaf(mb0, mb0, q0); q1 = fmaf(mb1, mb1, q1);
                cur = nxt;
            }
        }
        d_agg[n * 64 + lane]      = a0;
        d_agg[n * 64 + lane + 32] = a1;
        s0 += a0; s1 += a1;
    }
    __shared__ float sS[64], sQ[64];
    int t = threadIdx.x;
    if (t < 64) { sS[t] = 0.f; sQ[t] = 0.f; }
    __syncthreads();
    atomicAdd(&sS[lane], s0);      atomicAdd(&sS[lane + 32], s1);
    atomicAdd(&sQ[lane], q0);      atomicAdd(&sQ[lane + 32], q1);
    __syncthreads();
    double* st = d_stats + l * 256;
    if (t < 64) { atomicAdd(&st[t], (double)sS[t]); atomicAdd(&st[64 + t], (double)sQ[t]); }
}

// u = relu(affine(h)@Wu_h + affine(agg)@Wu_a + b) — smem weights (32KB),
// warp-per-4-nodes, no split-K, no loop barriers.
__global__ __launch_bounds__(256) void k_update(const float* __restrict__ upd_W,
                                                const float* __restrict__ upd_b, int l,
                                                const float* __restrict__ msg_gamma,
                                                const float* __restrict__ msg_beta,
                                                const float* __restrict__ upd_gamma,
                                                const float* __restrict__ upd_beta) {
    __shared__ float smsc[64], smsh[64], spsc[64], spsh[64];
    __shared__ float wsm[128 * 64];
    __shared__ float sbH[64], sbA[64];
    if (threadIdx.x < 64) {
        int f = threadIdx.x;
        const double* st = d_stats + l * 256;
        double mu  = st[f] / (double)NE;
        double var = st[64 + f] / (double)NE - mu * mu;
        float sc = msg_gamma[l * 64 + f] * rsqrtf((float)var + 1e-5f);
        smsc[f] = sc;
        smsh[f] = msg_beta[l * 64 + f] - (float)mu * sc;
    } else if (threadIdx.x < 128) {
        int f = threadIdx.x - 64;
        if (l > 0) {
            const double* st = d_stats + (l - 1) * 256 + 128;
            double mu  = st[f] / (double)NN;
            double var = st[64 + f] / (double)NN - mu * mu;
            float sc = upd_gamma[(l - 1) * 64 + f] * rsqrtf((float)var + 1e-5f);
            spsc[f] = sc;
            spsh[f] = upd_beta[(l - 1) * 64 + f] - (float)mu * sc;
        } else {
            spsc[f] = 1.f; spsh[f] = 0.f;
        }
    }
    __syncthreads();
    const float* W = upd_W + l * 128 * 64;
    for (int i = threadIdx.x; i < 8192; i += 256) {
        int k = i >> 6;
        float sc = (k < 64) ? spsc[k] : smsc[k - 64];
        wsm[i] = W[i] * sc;
    }
    if (threadIdx.x < 64) {
        int f = threadIdx.x;
        float bh = upd_b[l * 64 + f];
        for (int k = 0; k < 64; k++) bh = fmaf(spsh[k], W[k * 64 + f], bh);
        sbH[f] = bh;
    } else if (threadIdx.x < 128) {
        int f = threadIdx.x - 64;
        float ba = 0.f;
        for (int k = 0; k < 64; k++) ba = fmaf(smsh[k], W[(64 + k) * 64 + f], ba);
        sbA[f] = ba;
    }
    __syncthreads();
    int lane = threadIdx.x & 31;
    float bH0 = sbH[lane], bH1 = sbH[lane + 32];
    float bA0 = sbA[lane], bA1 = sbA[lane + 32];
    const float* in = (l == 0) ? d_h : d_u;
    float s0 = 0.f, q0 = 0.f, s1 = 0.f, q1 = 0.f;
    int gw = (blockIdx.x * 256 + threadIdx.x) >> 5;
    int nw = (gridDim.x * 256) >> 5;
    for (int g = gw * 4; g < NN; g += nw * 4) {
        float ih0[4], ih1[4], ia0[4], ia1[4], degf[4];
        bool act[4];
#pragma unroll
        for (int t = 0; t < 4; t++) {
            int n = g + t;
            act[t] = (n < NN);
            ih0[t] = act[t] ? in[(size_t)n * 64 + lane] : 0.f;
            ih1[t] = act[t] ? in[(size_t)n * 64 + lane + 32] : 0.f;
            ia0[t] = act[t] ? d_agg[(size_t)n * 64 + lane] : 0.f;
            ia1[t] = act[t] ? d_agg[(size_t)n * 64 + lane + 32] : 0.f;
            degf[t] = act[t] ? (float)__ldg(&d_cnt[n]) : 0.f;
        }
        float a0[4], a1[4];
#pragma unroll
        for (int t = 0; t < 4; t++) {
            a0[t] = fmaf(degf[t], bA0, bH0);
            a1[t] = fmaf(degf[t], bA1, bH1);
        }
#pragma unroll 16
        for (int k = 0; k < 32; k++) {
            float w0 = wsm[k * 64 + lane], w1 = wsm[k * 64 + lane + 32];
#pragma unroll
            for (int t = 0; t < 4; t++) {
                float bc = __shfl_sync(0xffffffffu, ih0[t], k);
                a0[t] = fmaf(bc, w0, a0[t]); a1[t] = fmaf(bc, w1, a1[t]);
            }
        }
#pragma unroll 16
        for (int k = 0; k < 32; k++) {
            float w0 = wsm[(k + 32) * 64 + lane], w1 = wsm[(k + 32) * 64 + lane + 32];
#pragma unroll
            for (int t = 0; t < 4; t++) {
                float bc = __shfl_sync(0xffffffffu, ih1[t], k);
                a0[t] = fmaf(bc, w0, a0[t]); a1[t] = fmaf(bc, w1, a1[t]);
            }
        }
#pragma unroll 16
        for (int k = 0; k < 32; k++) {
            float w0 = wsm[(k + 64) * 64 + lane], w1 = wsm[(k + 64) * 64 + lane + 32];
#pragma unroll
            for (int t = 0; t < 4; t++) {
                float bc = __shfl_sync(0xffffffffu, ia0[t], k);
                a0[t] = fmaf(bc, w0, a0[t]); a1[t] = fmaf(bc, w1, a1[t]);
            }
        }
#pragma unroll 16
        for (int k = 0; k < 32; k++) {
            float w0 = wsm[(k + 96) * 64 + lane], w1 = wsm[(k + 96) * 64 + lane + 32];
#pragma unroll
            for (int t = 0; t < 4; t++) {
                float bc = __shfl_sync(0xffffffffu, ia1[t], k);
                a0[t] = fmaf(bc, w0, a0[t]); a1[t] = fmaf(bc, w1, a1[t]);
            }
        }
#pragma unroll
        for (int t = 0; t < 4; t++) {
            if (act[t]) {
                float v0 = fmaxf(a0[t], 0.f);
                float v1 = fmaxf(a1[t], 0.f);
                int n = g + t;
                d_u[(size_t)n * 64 + lane]      = v0;
                d_u[(size_t)n * 64 + lane + 32] = v1;
                s0 += v0; q0 = fmaf(v0, v0, q0);
                s1 += v1; q1 = fmaf(v1, v1, q1);
            }
        }
    }
    __shared__ float sS[64], sQ[64];
    int t = threadIdx.x;
    if (t < 64) { sS[t] = 0.f; sQ[t] = 0.f; }
    __syncthreads();
    atomicAdd(&sS[lane], s0);      atomicAdd(&sS[lane + 32], s1);
    atomicAdd(&sQ[lane], q0);      atomicAdd(&sQ[lane + 32], q1);
    __syncthreads();
    double* st = d_stats + l * 256 + 128;
    if (t < 64) { atomicAdd(&st[t], (double)sS[t]); atomicAdd(&st[64 + t], (double)sQ[t]); }
}

// segmented pool (raw u + counts); self-cleans d_cnt
#define PL_BLOCKS 128
__global__ __launch_bounds__(256) void k_pool(const int* __restrict__ batch) {
    for (int i = blockIdx.x * blockDim.x + threadIdx.x; i < NN; i += PL_BLOCKS * 256)
        d_cnt[i] = 0;
    int lane = threadIdx.x & 31;
    int w = (blockIdx.x * 256 + threadIdx.x) >> 5;
    const int chunk = (NN + 1023) / 1024;
    int s = w * chunk, e = s + chunk;
    if (e > NN) e = NN;
    if (s >= NN) return;
    int curg = __ldg(&batch[s]);
    float A0 = 0.f, A1 = 0.f; int cnt = 0;
    for (int n = s; n < e; n++) {
        int g = __ldg(&batch[n]);
        if (g != curg) {
            atomicAdd(&d_gpool[curg * 64 + lane],      A0);
            atomicAdd(&d_gpool[curg * 64 + lane + 32], A1);
            if (lane == 0) atomicAdd(&d_gcnt[curg], cnt);
            curg = g; A0 = 0.f; A1 = 0.f; cnt = 0;
        }
        A0 += d_u[n * 64 + lane];
        A1 += d_u[n * 64 + lane + 32];
        cnt++;
    }
    atomicAdd(&d_gpool[curg * 64 + lane],      A0);
    atomicAdd(&d_gpool[curg * 64 + lane + 32], A1);
    if (lane == 0) atomicAdd(&d_gcnt[curg], cnt);
}

// readout: final BN affine inline; self-cleans pool/cnt
__global__ void k_readout(const float* __restrict__ r1_W, const float* __restrict__ r1_b,
                          const float* __restrict__ r2_W, const float* __restrict__ r2_b,
                          const float* __restrict__ upd_gamma,
                          const float* __restrict__ upd_beta,
                          float* __restrict__ out) {
    int gid = blockIdx.x, f = threadIdx.x;
    __shared__ float gv[64];
    const double* st = d_stats + 2 * 256 + 128;
    double mu  = st[f] / (double)NN;
    double var = st[64 + f] / (double)NN - mu * mu;
    float sc = upd_gamma[2 * 64 + f] * rsqrtf((float)var + 1e-5f);
    float sh = upd_beta[2 * 64 + f] - (float)mu * sc;
    float cntf = (float)d_gcnt[gid];
    gv[f] = fmaf(sc, d_gpool[gid * 64 + f], cntf * sh);
    __syncthreads();
    d_gpool[gid * 64 + f] = 0.f;
    if (f == 0) d_gcnt[gid] = 0;
    float acc = r1_b[f];
    for (int k = 0; k < 64; k++)
        acc = fmaf(gv[k], r1_W[k * 64 + f], acc);
    acc = fmaxf(acc, 0.f);
    float val = acc * r2_W[f];
    __shared__ float sh2[64];
    sh2[f] = val;
    __syncthreads();
    if (f < 32) sh2[f] += sh2[f + 32];
    __syncthreads();
    if (f < 16) sh2[f] += sh2[f + 16];
    __syncthreads();
    if (f < 8) sh2[f] += sh2[f + 8];
    __syncthreads();
    if (f < 4) sh2[f] += sh2[f + 4];
    __syncthreads();
    if (f < 2) sh2[f] += sh2[f + 2];
    __syncthreads();
    if (f == 0) out[gid] = sh2[0] + sh2[1] + r2_b[0];
}

extern "C" void kernel_launch(void* const* d_in, const int* in_sizes, int n_in,
                              void* d_out, int out_size) {
    const float* x         = (const float*)d_in[0];
    const float* edge_attr = (const float*)d_in[1];
    const int*   edge_idx  = (const int*)d_in[2];
    const int*   batch     = (const int*)d_in[3];
    const float* node_W    = (const float*)d_in[4];
    const float* node_b    = (const float*)d_in[5];
    const float* edge_W    = (const float*)d_in[6];
    const float* edge_b    = (const float*)d_in[7];
    const float* msg_W     = (const float*)d_in[8];
    const float* msg_b     = (const float*)d_in[9];
    const float* msg_gamma = (const float*)d_in[10];
    const float* msg_beta  = (const float*)d_in[11];
    const float* upd_W     = (const float*)d_in[12];
    const float* upd_b     = (const float*)d_in[13];
    const float* upd_gamma = (const float*)d_in[14];
    const float* upd_beta  = (const float*)d_in[15];
    const float* r1_W      = (const float*)d_in[16];
    const float* r1_b      = (const float*)d_in[17];
    const float* r2_W      = (const float*)d_in[18];
    const float* r2_b      = (const float*)d_in[19];
    float* out = (float*)d_out;

    const int* src = edge_idx;
    const int* dst = edge_idx + NE;

    k_scatter<<<2048, 256>>>(src, dst, edge_attr);                 // 0
    k_embedP<<<EM_BLOCKS + 1, 256>>>(x, node_W, node_b,
                                     edge_W, edge_b, msg_W, msg_b);// 1
    k_edge<<<4096, 128>>>(0);                                      // 2
    k_update<<<1024, 256>>>(upd_W, upd_b, 0, msg_gamma, msg_beta,
                            upd_gamma, upd_beta);                  // 3 <- profiled
    for (int l = 1; l < 3; l++) {
        k_p<<<1024, 256>>>(msg_W, l, upd_gamma, upd_beta);
        k_edge<<<4096, 128>>>(l);
        k_update<<<1024, 256>>>(upd_W, upd_b, l, msg_gamma, msg_beta,
                                upd_gamma, upd_beta);
    }
    k_pool<<<PL_BLOCKS, 256>>>(batch);
    k_readout<<<NG, 64>>>(r1_W, r1_b, r2_W, r2_b, upd_gamma, upd_beta, out);
}

// round 17
// speedup vs baseline: 1.4496x; 1.0173x over previous
#include <cuda_runtime.h>
#include <cuda_fp16.h>

#define NN 100000
#define NE 1600000
#define NG 1000
#define CAP 64

// ---------------- scratch (device globals; zero-initialized at load) ----------------
__device__ float  d_h[NN * 64];
__device__ float  d_p[NN * 64];     // float2-interleaved
__device__ float  d_u[NN * 64];
__device__ float  d_agg[NN * 64];
__device__ __half d_attrH[NE * 16];
__device__ float  d_gpool[NG * 64];
__device__ int    d_gcnt[NG];
__device__ int    d_cnt[NN];          // zero-init; re-zeroed by k_pool each run
__device__ int2   d_se[NN * CAP + 8];
__device__ float  d_C[3 * 16 * 64];
__device__ float  d_cv[3 * 64];
__device__ double d_stats[3 * 256];   // cleaned by k_scatter each run

__device__ __forceinline__ unsigned pkh2(float lo, float hi) {
    __half2 h = __floats2half2_rn(lo, hi);
    return *reinterpret_cast<unsigned*>(&h);
}
__device__ __forceinline__ float2 h2f(unsigned u) {
    return __half22float2(*reinterpret_cast<__half2*>(&u));
}

// launch 0: bucket scatter + fp16 attr conversion (fused) + stats clean
__global__ __launch_bounds__(256) void k_scatter(const int* __restrict__ src,
                                                 const int* __restrict__ dst,
                                                 const float* __restrict__ attr) {
    int tid0 = blockIdx.x * blockDim.x + threadIdx.x;
    if (tid0 < 3 * 256) d_stats[tid0] = 0.0;
    int stride = gridDim.x * blockDim.x;
    for (int i = tid0; i < NE; i += stride) {
        int d = dst[i];
        int pos = atomicAdd(&d_cnt[d], 1);
        if (pos < CAP) d_se[d * CAP + pos] = make_int2(src[i], i);
        const float4* a4 = (const float4*)(attr + (size_t)i * 16);
        float4 v0 = a4[0], v1 = a4[1], v2 = a4[2], v3 = a4[3];
        uint4 o0, o1;
        o0.x = pkh2(v0.x, v0.y); o0.y = pkh2(v0.z, v0.w);
        o0.z = pkh2(v1.x, v1.y); o0.w = pkh2(v1.z, v1.w);
        o1.x = pkh2(v2.x, v2.y); o1.y = pkh2(v2.z, v2.w);
        o1.z = pkh2(v3.x, v3.y); o1.w = pkh2(v3.z, v3.w);
        uint4* hp = (uint4*)(d_attrH + (size_t)i * 16);
        hp[0] = o0; hp[1] = o1;
    }
}

// launch 1: embed + FUSED p(l=0) + composite-C (last block)
#define EM_BLOCKS 512
__global__ __launch_bounds__(256) void k_embedP(const float* __restrict__ x,
                                                const float* __restrict__ node_W,
                                                const float* __restrict__ node_b,
                                                const float* __restrict__ edge_W,
                                                const float* __restrict__ edge_b,
                                                const float* __restrict__ msg_W,
                                                const float* __restrict__ msg_b) {
    int b = blockIdx.x;
    if (b < EM_BLOCKS) {
        int lane = threadIdx.x & 31;
        float w0[32], w1[32];
#pragma unroll
        for (int k = 0; k < 32; k++) { w0[k] = node_W[k * 64 + lane]; w1[k] = node_W[k * 64 + lane + 32]; }
        float b0 = node_b[lane], b1 = node_b[lane + 32];
        float mA[32], mB[32], mC[32], mD[32];
#pragma unroll
        for (int k = 0; k < 32; k++) {
            mA[k] = msg_W[k * 64 + lane];
            mB[k] = msg_W[(k + 32) * 64 + lane];
            mC[k] = msg_W[k * 64 + lane + 32];
            mD[k] = msg_W[(k + 32) * 64 + lane + 32];
        }
        float2* p2 = (float2*)d_p;
        int gw = (b * 256 + threadIdx.x) >> 5;
        int nw = (EM_BLOCKS * 256) >> 5;
        for (int n = gw; n < NN; n += nw) {
            float xv = x[n * 32 + lane];
            float a0 = b0, a1 = b1;
#pragma unroll
            for (int k = 0; k < 32; k++) {
                float bc = __shfl_sync(0xffffffffu, xv, k);
                a0 = fmaf(bc, w0[k], a0); a1 = fmaf(bc, w1[k], a1);
            }
            d_h[n * 64 + lane] = a0; d_h[n * 64 + lane + 32] = a1;
            float p0 = 0.f, p1 = 0.f;
#pragma unroll
            for (int k = 0; k < 32; k++) {
                float h0 = __shfl_sync(0xffffffffu, a0, k);
                float h1 = __shfl_sync(0xffffffffu, a1, k);
                p0 = fmaf(h0, mA[k], p0); p0 = fmaf(h1, mB[k], p0);
                p1 = fmaf(h0, mC[k], p1); p1 = fmaf(h1, mD[k], p1);
            }
            p2[(size_t)n * 32 + lane] = make_float2(p0, p1);
        }
    } else {
        int t = threadIdx.x;
        if (t < 192) {
            int l = t >> 6, f = t & 63;
            const float* Wm = msg_W + l * 96 * 64 + 64 * 64;
            for (int kk = 0; kk < 16; kk++) {
                float s = 0.f;
                for (int j = 0; j < 32; j++) s = fmaf(edge_W[kk * 32 + j], Wm[j * 64 + f], s);
                d_C[l * 1024 + kk * 64 + f] = s;
            }
            float cv = msg_b[l * 64 + f];
            for (int j = 0; j < 32; j++) cv = fmaf(edge_b[j], Wm[j * 64 + f], cv);
            d_cv[l * 64 + f] = cv;
        }
    }
}

// p = affine(u) @ msg_W[l][0:64,:] for l=1,2 — smem weights, warp-per-8-nodes
__global__ __launch_bounds__(256) void k_p(const float* __restrict__ msg_W, int l,
                                           const float* __restrict__ upd_gamma,
                                           const float* __restrict__ upd_beta) {
    __shared__ float ssc[64], ssh[64];
    __shared__ float ws[64 * 64];
    __shared__ float sbias[64];
    if (threadIdx.x < 64) {
        int f = threadIdx.x;
        const double* st = d_stats + (l - 1) * 256 + 128;
        double mu  = st[f] / (double)NN;
        double var = st[64 + f] / (double)NN - mu * mu;
        float sc = upd_gamma[(l - 1) * 64 + f] * rsqrtf((float)var + 1e-5f);
        ssc[f] = sc;
        ssh[f] = upd_beta[(l - 1) * 64 + f] - (float)mu * sc;
    }
    __syncthreads();
    const float* W = msg_W + l * 96 * 64;
    for (int i = threadIdx.x; i < 4096; i += 256)
        ws[i] = W[i] * ssc[i >> 6];
    if (threadIdx.x < 64) {
        int f = threadIdx.x;
        float bsum = 0.f;
        for (int k = 0; k < 64; k++) bsum = fmaf(ssh[k], W[k * 64 + f], bsum);
        sbias[f] = bsum;
    }
    __syncthreads();
    int lane = threadIdx.x & 31;
    float bias0 = sbias[lane], bias1 = sbias[lane + 32];
    const float* in = d_u;
    float2* p2 = (float2*)d_p;
    int gw = (blockIdx.x * 256 + threadIdx.x) >> 5;
    int nw = (gridDim.x * 256) >> 5;
    for (int g = gw * 8; g < NN; g += nw * 8) {
        float iv0[8], iv1[8];
#pragma unroll
        for (int t = 0; t < 8; t++) {
            int n = g + t;
            bool a = (n < NN);
            iv0[t] = a ? in[(size_t)n * 64 + lane] : 0.f;
            iv1[t] = a ? in[(size_t)n * 64 + lane + 32] : 0.f;
        }
        float a0[8], a1[8];
#pragma unroll
        for (int t = 0; t < 8; t++) { a0[t] = bias0; a1[t] = bias1; }
#pragma unroll 8
        for (int k = 0; k < 32; k++) {
            float w0 = ws[k * 64 + lane], w1 = ws[k * 64 + lane + 32];
#pragma unroll
            for (int t = 0; t < 8; t++) {
                float bc = __shfl_sync(0xffffffffu, iv0[t], k);
                a0[t] = fmaf(bc, w0, a0[t]); a1[t] = fmaf(bc, w1, a1[t]);
            }
        }
#pragma unroll 8
        for (int k = 0; k < 32; k++) {
            float w0 = ws[(k + 32) * 64 + lane], w1 = ws[(k + 32) * 64 + lane + 32];
#pragma unroll
            for (int t = 0; t < 8; t++) {
                float bc = __shfl_sync(0xffffffffu, iv1[t], k);
                a0[t] = fmaf(bc, w0, a0[t]); a1[t] = fmaf(bc, w1, a1[t]);
            }
        }
#pragma unroll
        for (int t = 0; t < 8; t++)
            if (g + t < NN)
                p2[(size_t)(g + t) * 32 + lane] = make_float2(a0[t], a1[t]);
    }
}

// HOT: R13-exact 2-edge k_edge (unchanged control)
__global__ __launch_bounds__(128) void k_edge(int l) {
    int lane = threadIdx.x & 31;
    const float* C = d_C + l * 1024;
    float cw0[16], cw1[16];
#pragma unroll
    for (int k = 0; k < 16; k++) { cw0[k] = C[k * 64 + lane]; cw1[k] = C[k * 64 + lane + 32]; }
    float cb0 = d_cv[l * 64 + lane], cb1 = d_cv[l * 64 + lane + 32];
    float s0 = 0.f, q0 = 0.f, s1 = 0.f, q1 = 0.f;
    const float2* p2 = (const float2*)d_p;
    int gw = (blockIdx.x * blockDim.x + threadIdx.x) >> 5;
    int nw = (gridDim.x * blockDim.x) >> 5;
    for (int n = gw; n < NN; n += nw) {
        int deg = __ldg(&d_cnt[n]);
        deg = (deg > CAP) ? CAP : deg;
        const int2* bp = d_se + (size_t)n * CAP;
        float a0 = 0.f, a1 = 0.f;
        if (deg > 0) {
            int4 cur = __ldg((const int4*)bp);
            for (int j = 0; j < deg; j += 2) {
                int4 nxt = __ldg((const int4*)(bp + j + 2));
                float2 pa = __ldg(&p2[(size_t)cur.x * 32 + lane]);
                float2 pb = __ldg(&p2[(size_t)cur.z * 32 + lane]);
                const uint4* apA = (const uint4*)(d_attrH + (size_t)cur.y * 16);
                const uint4* apB = (const uint4*)(d_attrH + (size_t)cur.w * 16);
                uint4 Aa = __ldg(apA), Ab = __ldg(apA + 1);
                uint4 Ba = __ldg(apB), Bb = __ldg(apB + 1);
                float flagB = (j + 1 < deg) ? 1.f : 0.f;
                float2 A0 = h2f(Aa.x), A1 = h2f(Aa.y), A2 = h2f(Aa.z), A3 = h2f(Aa.w);
                float2 A4 = h2f(Ab.x), A5 = h2f(Ab.y), A6 = h2f(Ab.z), A7 = h2f(Ab.w);
                float2 B0 = h2f(Ba.x), B1 = h2f(Ba.y), B2 = h2f(Ba.z), B3 = h2f(Ba.w);
                float2 B4 = h2f(Bb.x), B5 = h2f(Bb.y), B6 = h2f(Bb.z), B7 = h2f(Bb.w);
                float ma0 = pa.x + cb0, ma1 = pa.y + cb1;
                float mb0 = pb.x + cb0, mb1 = pb.y + cb1;
                ma0 = fmaf(A0.x, cw0[0], ma0);  ma1 = fmaf(A0.x, cw1[0], ma1);
                mb0 = fmaf(B0.x, cw0[0], mb0);  mb1 = fmaf(B0.x, cw1[0], mb1);
                ma0 = fmaf(A0.y, cw0[1], ma0);  ma1 = fmaf(A0.y, cw1[1], ma1);
                mb0 = fmaf(B0.y, cw0[1], mb0);  mb1 = fmaf(B0.y, cw1[1], mb1);
                ma0 = fmaf(A1.x, cw0[2], ma0);  ma1 = fmaf(A1.x, cw1[2], ma1);
                mb0 = fmaf(B1.x, cw0[2], mb0);  mb1 = fmaf(B1.x, cw1[2], mb1);
                ma0 = fmaf(A1.y, cw0[3], ma0);  ma1 = fmaf(A1.y, cw1[3], ma1);
                mb0 = fmaf(B1.y, cw0[3], mb0);  mb1 = fmaf(B1.y, cw1[3], mb1);
                ma0 = fmaf(A2.x, cw0[4], ma0);  ma1 = fmaf(A2.x, cw1[4], ma1);
                mb0 = fmaf(B2.x, cw0[4], mb0);  mb1 = fmaf(B2.x, cw1[4], mb1);
                ma0 = fmaf(A2.y, cw0[5], ma0);  ma1 = fmaf(A2.y, cw1[5], ma1);
                mb0 = fmaf(B2.y, cw0[5], mb0);  mb1 = fmaf(B2.y, cw1[5], mb1);
                ma0 = fmaf(A3.x, cw0[6], ma0);  ma1 = fmaf(A3.x, cw1[6], ma1);
                mb0 = fmaf(B3.x, cw0[6], mb0);  mb1 = fmaf(B3.x, cw1[6], mb1);
                ma0 = fmaf(A3.y, cw0[7], ma0);  ma1 = fmaf(A3.y, cw1[7], ma1);
                mb0 = fmaf(B3.y, cw0[7], mb0);  mb1 = fmaf(B3.y, cw1[7], mb1);
                ma0 = fmaf(A4.x, cw0[8], ma0);  ma1 = fmaf(A4.x, cw1[8], ma1);
                mb0 = fmaf(B4.x, cw0[8], mb0);  mb1 = fmaf(B4.x, cw1[8], mb1);
                ma0 = fmaf(A4.y, cw0[9], ma0);  ma1 = fmaf(A4.y, cw1[9], ma1);
                mb0 = fmaf(B4.y, cw0[9], mb0);  mb1 = fmaf(B4.y, cw1[9], mb1);
                ma0 = fmaf(A5.x, cw0[10], ma0); ma1 = fmaf(A5.x, cw1[10], ma1);
                mb0 = fmaf(B5.x, cw0[10], mb0); mb1 = fmaf(B5.x, cw1[10], mb1);
                ma0 = fmaf(A5.y, cw0[11], ma0); ma1 = fmaf(A5.y, cw1[11], ma1);
                mb0 = fmaf(B5.y, cw0[11], mb0); mb1 = fmaf(B5.y, cw1[11], mb1);
                ma0 = fmaf(A6.x, cw0[12], ma0); ma1 = fmaf(A6.x, cw1[12], ma1);
                mb0 = fmaf(B6.x, cw0[12], mb0); mb1 = fmaf(B6.x, cw1[12], mb1);
                ma0 = fmaf(A6.y, cw0[13], ma0); ma1 = fmaf(A6.y, cw1[13], ma1);
                mb0 = fmaf(B6.y, cw0[13], mb0); mb1 = fmaf(B6.y, cw1[13], mb1);
                ma0 = fmaf(A7.x, cw0[14], ma0); ma1 = fmaf(A7.x, cw1[14], ma1);
                mb0 = fmaf(B7.x, cw0[14], mb0); mb1 = fmaf(B7.x, cw1[14], mb1);
                ma0 = fmaf(A7.y, cw0[15], ma0); ma1 = fmaf(A7.y, cw1[15], ma1);
                mb0 = fmaf(B7.y, cw0[15], mb0); mb1 = fmaf(B7.y, cw1[15], mb1);
                ma0 = fmaxf(ma0, 0.f); ma1 = fmaxf(ma1, 0.f);
                mb0 = fmaxf(mb0, 0.f) * flagB; mb1 = fmaxf(mb1, 0.f) * flagB;
                a0 += ma0 + mb0; a1 += ma1 + mb1;
                q0 = fmaf(ma0, ma0, q0); q1 = fmaf(ma1, ma1, q1);
                q0 = fmaf(mb0, mb0, q0); q1 = fmaf(mb1, mb1, q1);
                cur = nxt;
            }
        }
        d_agg[n * 64 + lane]      = a0;
        d_agg[n * 64 + lane + 32] = a1;
        s0 += a0; s1 += a1;
    }
    __shared__ float sS[64], sQ[64];
    int t = threadIdx.x;
    if (t < 64) { sS[t] = 0.f; sQ[t] = 0.f; }
    __syncthreads();
    atomicAdd(&sS[lane], s0);      atomicAdd(&sS[lane + 32], s1);
    atomicAdd(&sQ[lane], q0);      atomicAdd(&sQ[lane + 32], q1);
    __syncthreads();
    double* st = d_stats + l * 256;
    if (t < 64) { atomicAdd(&st[t], (double)sS[t]); atomicAdd(&st[64 + t], (double)sQ[t]); }
}

// u = relu(affine(h)@Wu_h + affine(agg)@Wu_a + b) — smem weights, warp-per-8-nodes
__global__ __launch_bounds__(256) void k_update(const float* __restrict__ upd_W,
                                                const float* __restrict__ upd_b, int l,
                                                const float* __restrict__ msg_gamma,
                                                const float* __restrict__ msg_beta,
                                                const float* __restrict__ upd_gamma,
                                                const float* __restrict__ upd_beta) {
    __shared__ float smsc[64], smsh[64], spsc[64], spsh[64];
    __shared__ float wsm[128 * 64];
    __shared__ float sbH[64], sbA[64];
    if (threadIdx.x < 64) {
        int f = threadIdx.x;
        const double* st = d_stats + l * 256;
        double mu  = st[f] / (double)NE;
        double var = st[64 + f] / (double)NE - mu * mu;
        float sc = msg_gamma[l * 64 + f] * rsqrtf((float)var + 1e-5f);
        smsc[f] = sc;
        smsh[f] = msg_beta[l * 64 + f] - (float)mu * sc;
    } else if (threadIdx.x < 128) {
        int f = threadIdx.x - 64;
        if (l > 0) {
            const double* st = d_stats + (l - 1) * 256 + 128;
            double mu  = st[f] / (double)NN;
            double var = st[64 + f] / (double)NN - mu * mu;
            float sc = upd_gamma[(l - 1) * 64 + f] * rsqrtf((float)var + 1e-5f);
            spsc[f] = sc;
            spsh[f] = upd_beta[(l - 1) * 64 + f] - (float)mu * sc;
        } else {
            spsc[f] = 1.f; spsh[f] = 0.f;
        }
    }
    __syncthreads();
    const float* W = upd_W + l * 128 * 64;
    for (int i = threadIdx.x; i < 8192; i += 256) {
        int k = i >> 6;
        float sc = (k < 64) ? spsc[k] : smsc[k - 64];
        wsm[i] = W[i] * sc;
    }
    if (threadIdx.x < 64) {
        int f = threadIdx.x;
        float bh = upd_b[l * 64 + f];
        for (int k = 0; k < 64; k++) bh = fmaf(spsh[k], W[k * 64 + f], bh);
        sbH[f] = bh;
    } else if (threadIdx.x < 128) {
        int f = threadIdx.x - 64;
        float ba = 0.f;
        for (int k = 0; k < 64; k++) ba = fmaf(smsh[k], W[(64 + k) * 64 + f], ba);
        sbA[f] = ba;
    }
    __syncthreads();
    int lane = threadIdx.x & 31;
    float bH0 = sbH[lane], bH1 = sbH[lane + 32];
    float bA0 = sbA[lane], bA1 = sbA[lane + 32];
    const float* in = (l == 0) ? d_h : d_u;
    float s0 = 0.f, q0 = 0.f, s1 = 0.f, q1 = 0.f;
    int gw = (blockIdx.x * 256 + threadIdx.x) >> 5;
    int nw = (gridDim.x * 256) >> 5;
    for (int g = gw * 8; g < NN; g += nw * 8) {
        float ih0[8], ih1[8], ia0[8], ia1[8];
        float a0[8], a1[8];
#pragma unroll
        for (int t = 0; t < 8; t++) {
            int n = g + t;
            bool a = (n < NN);
            ih0[t] = a ? in[(size_t)n * 64 + lane] : 0.f;
            ih1[t] = a ? in[(size_t)n * 64 + lane + 32] : 0.f;
            ia0[t] = a ? d_agg[(size_t)n * 64 + lane] : 0.f;
            ia1[t] = a ? d_agg[(size_t)n * 64 + lane + 32] : 0.f;
            float degf = a ? (float)__ldg(&d_cnt[n]) : 0.f;
            a0[t] = fmaf(degf, bA0, bH0);
            a1[t] = fmaf(degf, bA1, bH1);
        }
#pragma unroll 8
        for (int k = 0; k < 32; k++) {
            float w0 = wsm[k * 64 + lane], w1 = wsm[k * 64 + lane + 32];
#pragma unroll
            for (int t = 0; t < 8; t++) {
                float bc = __shfl_sync(0xffffffffu, ih0[t], k);
                a0[t] = fmaf(bc, w0, a0[t]); a1[t] = fmaf(bc, w1, a1[t]);
            }
        }
#pragma unroll 8
        for (int k = 0; k < 32; k++) {
            float w0 = wsm[(k + 32) * 64 + lane], w1 = wsm[(k + 32) * 64 + lane + 32];
#pragma unroll
            for (int t = 0; t < 8; t++) {
                float bc = __shfl_sync(0xffffffffu, ih1[t], k);
                a0[t] = fmaf(bc, w0, a0[t]); a1[t] = fmaf(bc, w1, a1[t]);
            }
        }
#pragma unroll 8
        for (int k = 0; k < 32; k++) {
            float w0 = wsm[(k + 64) * 64 + lane], w1 = wsm[(k + 64) * 64 + lane + 32];
#pragma unroll
            for (int t = 0; t < 8; t++) {
                float bc = __shfl_sync(0xffffffffu, ia0[t], k);
                a0[t] = fmaf(bc, w0, a0[t]); a1[t] = fmaf(bc, w1, a1[t]);
            }
        }
#pragma unroll 8
        for (int k = 0; k < 32; k++) {
            float w0 = wsm[(k + 96) * 64 + lane], w1 = wsm[(k + 96) * 64 + lane + 32];
#pragma unroll
            for (int t = 0; t < 8; t++) {
                float bc = __shfl_sync(0xffffffffu, ia1[t], k);
                a0[t] = fmaf(bc, w0, a0[t]); a1[t] = fmaf(bc, w1, a1[t]);
            }
        }
#pragma unroll
        for (int t = 0; t < 8; t++) {
            if (g + t < NN) {
                float v0 = fmaxf(a0[t], 0.f);
                float v1 = fmaxf(a1[t], 0.f);
                int n = g + t;
                d_u[(size_t)n * 64 + lane]      = v0;
                d_u[(size_t)n * 64 + lane + 32] = v1;
                s0 += v0; q0 = fmaf(v0, v0, q0);
                s1 += v1; q1 = fmaf(v1, v1, q1);
            }
        }
    }
    __shared__ float sS[64], sQ[64];
    int t = threadIdx.x;
    if (t < 64) { sS[t] = 0.f; sQ[t] = 0.f; }
    __syncthreads();
    atomicAdd(&sS[lane], s0);      atomicAdd(&sS[lane + 32], s1);
    atomicAdd(&sQ[lane], q0);      atomicAdd(&sQ[lane + 32], q1);
    __syncthreads();
    double* st = d_stats + l * 256 + 128;
    if (t < 64) { atomicAdd(&st[t], (double)sS[t]); atomicAdd(&st[64 + t], (double)sQ[t]); }
}

// segmented pool (raw u + counts); self-cleans d_cnt
#define PL_BLOCKS 128
__global__ __launch_bounds__(256) void k_pool(const int* __restrict__ batch) {
    for (int i = blockIdx.x * blockDim.x + threadIdx.x; i < NN; i += PL_BLOCKS * 256)
        d_cnt[i] = 0;
    int lane = threadIdx.x & 31;
    int w = (blockIdx.x * 256 + threadIdx.x) >> 5;
    const int chunk = (NN + 1023) / 1024;
    int s = w * chunk, e = s + chunk;
    if (e > NN) e = NN;
    if (s >= NN) return;
    int curg = __ldg(&batch[s]);
    float A0 = 0.f, A1 = 0.f; int cnt = 0;
    for (int n = s; n < e; n++) {
        int g = __ldg(&batch[n]);
        if (g != curg) {
            atomicAdd(&d_gpool[curg * 64 + lane],      A0);
            atomicAdd(&d_gpool[curg * 64 + lane + 32], A1);
            if (lane == 0) atomicAdd(&d_gcnt[curg], cnt);
            curg = g; A0 = 0.f; A1 = 0.f; cnt = 0;
        }
        A0 += d_u[n * 64 + lane];
        A1 += d_u[n * 64 + lane + 32];
        cnt++;
    }
    atomicAdd(&d_gpool[curg * 64 + lane],      A0);
    atomicAdd(&d_gpool[curg * 64 + lane + 32], A1);
    if (lane == 0) atomicAdd(&d_gcnt[curg], cnt);
}

// readout: final BN affine inline; self-cleans pool/cnt
__global__ void k_readout(const float* __restrict__ r1_W, const float* __restrict__ r1_b,
                          const float* __restrict__ r2_W, const float* __restrict__ r2_b,
                          const float* __restrict__ upd_gamma,
                          const float* __restrict__ upd_beta,
                          float* __restrict__ out) {
    int gid = blockIdx.x, f = threadIdx.x;
    __shared__ float gv[64];
    const double* st = d_stats + 2 * 256 + 128;
    double mu  = st[f] / (double)NN;
    double var = st[64 + f] / (double)NN - mu * mu;
    float sc = upd_gamma[2 * 64 + f] * rsqrtf((float)var + 1e-5f);
    float sh = upd_beta[2 * 64 + f] - (float)mu * sc;
    float cntf = (float)d_gcnt[gid];
    gv[f] = fmaf(sc, d_gpool[gid * 64 + f], cntf * sh);
    __syncthreads();
    d_gpool[gid * 64 + f] = 0.f;
    if (f == 0) d_gcnt[gid] = 0;
    float acc = r1_b[f];
    for (int k = 0; k < 64; k++)
        acc = fmaf(gv[k], r1_W[k * 64 + f], acc);
    acc = fmaxf(acc, 0.f);
    float val = acc * r2_W[f];
    __shared__ float sh2[64];
    sh2[f] = val;
    __syncthreads();
    if (f < 32) sh2[f] += sh2[f + 32];
    __syncthreads();
    if (f < 16) sh2[f] += sh2[f + 16];
    __syncthreads();
    if (f < 8) sh2[f] += sh2[f + 8];
    __syncthreads();
    if (f < 4) sh2[f] += sh2[f + 4];
    __syncthreads();
    if (f < 2) sh2[f] += sh2[f + 2];
    __syncthreads();
    if (f == 0) out[gid] = sh2[0] + sh2[1] + r2_b[0];
}

extern "C" void kernel_launch(void* const* d_in, const int* in_sizes, int n_in,
                              void* d_out, int out_size) {
    const float* x         = (const float*)d_in[0];
    const float* edge_attr = (const float*)d_in[1];
    const int*   edge_idx  = (const int*)d_in[2];
    const int*   batch     = (const int*)d_in[3];
    const float* node_W    = (const float*)d_in[4];
    const float* node_b    = (const float*)d_in[5];
    const float* edge_W    = (const float*)d_in[6];
    const float* edge_b    = (const float*)d_in[7];
    const float* msg_W     = (const float*)d_in[8];
    const float* msg_b     = (const float*)d_in[9];
    const float* msg_gamma = (const float*)d_in[10];
    const float* msg_beta  = (const float*)d_in[11];
    const float* upd_W     = (const float*)d_in[12];
    const float* upd_b     = (const float*)d_in[13];
    const float* upd_gamma = (const float*)d_in[14];
    const float* upd_beta  = (const float*)d_in[15];
    const float* r1_W      = (const float*)d_in[16];
    const float* r1_b      = (const float*)d_in[17];
    const float* r2_W      = (const float*)d_in[18];
    const float* r2_b      = (const float*)d_in[19];
    float* out = (float*)d_out;

    const int* src = edge_idx;
    const int* dst = edge_idx + NE;

    k_scatter<<<2048, 256>>>(src, dst, edge_attr);                 // 0
    k_embedP<<<EM_BLOCKS + 1, 256>>>(x, node_W, node_b,
                                     edge_W, edge_b, msg_W, msg_b);// 1
    k_edge<<<4096, 128>>>(0);                                      // 2
    k_update<<<1024, 256>>>(upd_W, upd_b, 0, msg_gamma, msg_beta,
                            upd_gamma, upd_beta);                  // 3 <- profiled
    for (int l = 1; l < 3; l++) {
        k_p<<<1024, 256>>>(msg_W, l, upd_gamma, upd_beta);
        k_edge<<<4096, 128>>>(l);
        k_update<<<1024, 256>>>(upd_W, upd_b, l, msg_gamma, msg_beta,
                                upd_gamma, upd_beta);
    }
    k_pool<<<PL_BLOCKS, 256>>>(batch);
    k_readout<<<NG, 64>>>(r1_W, r1_b, r2_W, r2_b, upd_gamma, upd_beta, out);
}